// round 11
// baseline (speedup 1.0000x reference)
#include <cuda_runtime.h>
#include <math.h>

#define DIM 128
#define BM 64
#define LDT 132   // padded row stride for the 64xD SMEM tile
#define MAXN 50000
#define MAXE 600000

// Scratch (module-load allocated, not counted against kernel_launch)
__device__ float g_msg[(size_t)MAXN * DIM];
__device__ float g_sum[(size_t)MAXN * DIM];
__device__ int   g_cnt[MAXN];

// ---------------------------------------------------------------------------
// Zero the aggregation buffers
// ---------------------------------------------------------------------------
__global__ void hmp_zero_kernel(int n) {
    int stride = gridDim.x * blockDim.x;
    int tid = blockIdx.x * blockDim.x + threadIdx.x;
    float4* s4 = reinterpret_cast<float4*>(g_sum);
    int tot4 = n * (DIM / 4);
    for (int i = tid; i < tot4; i += stride) s4[i] = make_float4(0.f, 0.f, 0.f, 0.f);
    for (int i = tid; i < n; i += stride) g_cnt[i] = 0;
}

// ---------------------------------------------------------------------------
// Shared GEMM stage: acc[4][8] = sT(64x128, ld=LDT) @ sW(128x128)
// 256 threads as 16x16; thread (ty,tx) owns rows ty*4..+3, cols tx*8..+7
// ---------------------------------------------------------------------------
__device__ __forceinline__ void gemm_stage(const float* __restrict__ sT,
                                           const float* __restrict__ sW,
                                           int tx, int ty, float acc[4][8]) {
#pragma unroll
    for (int i = 0; i < 4; ++i)
#pragma unroll
        for (int j = 0; j < 8; ++j) acc[i][j] = 0.f;

#pragma unroll 4
    for (int k = 0; k < DIM; ++k) {
        float a0 = sT[(ty * 4 + 0) * LDT + k];
        float a1 = sT[(ty * 4 + 1) * LDT + k];
        float a2 = sT[(ty * 4 + 2) * LDT + k];
        float a3 = sT[(ty * 4 + 3) * LDT + k];
        const float4* wr = reinterpret_cast<const float4*>(sW + k * DIM + tx * 8);
        float4 bA = wr[0];
        float4 bB = wr[1];
        float b[8] = {bA.x, bA.y, bA.z, bA.w, bB.x, bB.y, bB.z, bB.w};
#pragma unroll
        for (int j = 0; j < 8; ++j) {
            acc[0][j] = fmaf(a0, b[j], acc[0][j]);
            acc[1][j] = fmaf(a1, b[j], acc[1][j]);
            acc[2][j] = fmaf(a2, b[j], acc[2][j]);
            acc[3][j] = fmaf(a3, b[j], acc[3][j]);
        }
    }
}

// ---------------------------------------------------------------------------
// Per-node message MLP: g_msg = relu(logmap0(x) @ W1 + b1) @ W2 + b2
// ---------------------------------------------------------------------------
__global__ __launch_bounds__(256, 1) void hmp_msg_kernel(
    const float* __restrict__ x,
    const float* __restrict__ w1, const float* __restrict__ b1,
    const float* __restrict__ w2, const float* __restrict__ b2, int n)
{
    extern __shared__ float smem[];
    float* sW1  = smem;
    float* sW2  = smem + DIM * DIM;
    float* sT   = smem + 2 * DIM * DIM;
    float* sRow = sT + BM * LDT;

    int tid = threadIdx.x;
    int m0 = blockIdx.x * BM;
    int rows = n - m0; if (rows > BM) rows = BM;

    for (int i = tid; i < DIM * DIM; i += 256) { sW1[i] = w1[i]; sW2[i] = w2[i]; }

    for (int i = tid; i < BM * DIM; i += 256) {
        int m = i >> 7, k = i & (DIM - 1);
        sT[m * LDT + k] = (m < rows) ? x[(size_t)(m0 + m) * DIM + k] : 0.f;
    }
    __syncthreads();

    // logmap0 scale per row: artanh(clip(||x||)) / clip(||x||)
    int warp = tid >> 5, lane = tid & 31;
#pragma unroll
    for (int r8 = 0; r8 < 8; ++r8) {
        int m = warp * 8 + r8;
        float4 v = reinterpret_cast<const float4*>(sT + m * LDT)[lane];
        float p = v.x * v.x + v.y * v.y + v.z * v.z + v.w * v.w;
#pragma unroll
        for (int o = 16; o; o >>= 1) p += __shfl_xor_sync(0xffffffffu, p, o);
        if (lane == 0) {
            float nrm = sqrtf(p);
            float nc = fminf(fmaxf(nrm, 1e-8f), 1.f - 1e-5f);
            sRow[m] = atanhf(nc) / nc;
        }
    }
    __syncthreads();
    for (int i = tid; i < BM * DIM; i += 256) {
        int m = i >> 7, k = i & (DIM - 1);
        sT[m * LDT + k] *= sRow[m];
    }
    __syncthreads();

    int tx = tid & 15, ty = tid >> 4;
    float acc[4][8];
    gemm_stage(sT, sW1, tx, ty, acc);
    __syncthreads();   // all reads of sT done before overwrite
#pragma unroll
    for (int i = 0; i < 4; ++i) {
        int m = ty * 4 + i;
#pragma unroll
        for (int j = 0; j < 8; ++j) {
            float v = acc[i][j] + __ldg(b1 + tx * 8 + j);
            sT[m * LDT + tx * 8 + j] = fmaxf(v, 0.f);
        }
    }
    __syncthreads();
    gemm_stage(sT, sW2, tx, ty, acc);
#pragma unroll
    for (int i = 0; i < 4; ++i) {
        int m = ty * 4 + i;
        if (m < rows) {
#pragma unroll
            for (int j = 0; j < 8; ++j)
                g_msg[(size_t)(m0 + m) * DIM + tx * 8 + j] =
                    acc[i][j] + __ldg(b2 + tx * 8 + j);
        }
    }
}

// ---------------------------------------------------------------------------
// Edge scatter: g_sum[row] += g_msg[col]; g_cnt[row] += 1  (warp per edge)
// ---------------------------------------------------------------------------
__global__ void hmp_scatter_kernel(const int* __restrict__ rows,
                                   const int* __restrict__ cols, int e)
{
    int idx = blockIdx.x * blockDim.x + threadIdx.x;
    int ed = idx >> 5;
    int lane = idx & 31;
    if (ed >= e) return;
    int r = __ldg(rows + ed);
    int c = __ldg(cols + ed);
    float4 v = reinterpret_cast<const float4*>(g_msg + (size_t)c * DIM)[lane];
    float* dst = g_sum + (size_t)r * DIM + lane * 4;
    atomicAdd(dst + 0, v.x);
    atomicAdd(dst + 1, v.y);
    atomicAdd(dst + 2, v.z);
    atomicAdd(dst + 3, v.w);
    if (lane == 0) atomicAdd(g_cnt + r, 1);
}

// ---------------------------------------------------------------------------
// Update MLP + expmap0:
// out = expmap0( relu( (g_sum/(cnt+eps)) @ Wu1 + bu1 ) @ Wu2 + bu2 )
// ---------------------------------------------------------------------------
__global__ __launch_bounds__(256, 1) void hmp_upd_kernel(
    const float* __restrict__ w1, const float* __restrict__ b1,
    const float* __restrict__ w2, const float* __restrict__ b2,
    float* __restrict__ out, int n)
{
    extern __shared__ float smem[];
    float* sW1  = smem;
    float* sW2  = smem + DIM * DIM;
    float* sT   = smem + 2 * DIM * DIM;
    float* sRow = sT + BM * LDT;

    int tid = threadIdx.x;
    int m0 = blockIdx.x * BM;
    int rows = n - m0; if (rows > BM) rows = BM;

    for (int i = tid; i < DIM * DIM; i += 256) { sW1[i] = w1[i]; sW2[i] = w2[i]; }

    if (tid < BM) {
        float inv = 0.f;
        if (tid < rows) inv = 1.f / ((float)g_cnt[m0 + tid] + 1e-8f);
        sRow[tid] = inv;
    }
    __syncthreads();
    for (int i = tid; i < BM * DIM; i += 256) {
        int m = i >> 7, k = i & (DIM - 1);
        float v = (m < rows) ? g_sum[(size_t)(m0 + m) * DIM + k] : 0.f;
        sT[m * LDT + k] = v * sRow[m];
    }
    __syncthreads();

    int tx = tid & 15, ty = tid >> 4;
    float acc[4][8];
    gemm_stage(sT, sW1, tx, ty, acc);
    __syncthreads();
#pragma unroll
    for (int i = 0; i < 4; ++i) {
        int m = ty * 4 + i;
#pragma unroll
        for (int j = 0; j < 8; ++j) {
            float v = acc[i][j] + __ldg(b1 + tx * 8 + j);
            sT[m * LDT + tx * 8 + j] = fmaxf(v, 0.f);
        }
    }
    __syncthreads();
    gemm_stage(sT, sW2, tx, ty, acc);
    __syncthreads();   // stage-2 reads of sT done before overwrite
#pragma unroll
    for (int i = 0; i < 4; ++i) {
        int m = ty * 4 + i;
#pragma unroll
        for (int j = 0; j < 8; ++j) {
            acc[i][j] += __ldg(b2 + tx * 8 + j);
            sT[m * LDT + tx * 8 + j] = acc[i][j];
        }
    }
    __syncthreads();

    // expmap0 scale per row: tanh(max(||z||,eps)) / max(||z||,eps)
    int warp = tid >> 5, lane = tid & 31;
#pragma unroll
    for (int r8 = 0; r8 < 8; ++r8) {
        int m = warp * 8 + r8;
        float4 v = reinterpret_cast<const float4*>(sT + m * LDT)[lane];
        float p = v.x * v.x + v.y * v.y + v.z * v.z + v.w * v.w;
#pragma unroll
        for (int o = 16; o; o >>= 1) p += __shfl_xor_sync(0xffffffffu, p, o);
        if (lane == 0) {
            float nrm = sqrtf(p);
            float nc = fmaxf(nrm, 1e-8f);
            sRow[m] = tanhf(nc) / nc;
        }
    }
    __syncthreads();
#pragma unroll
    for (int i = 0; i < 4; ++i) {
        int m = ty * 4 + i;
        if (m < rows) {
            float s = sRow[m];
#pragma unroll
            for (int j = 0; j < 8; ++j)
                out[(size_t)(m0 + m) * DIM + tx * 8 + j] = acc[i][j] * s;
        }
    }
}

// ---------------------------------------------------------------------------
extern "C" void kernel_launch(void* const* d_in, const int* in_sizes, int n_in,
                              void* d_out, int out_size) {
    const float* x   = (const float*)d_in[0];
    const int*   ei  = (const int*)d_in[1];
    const float* wm1 = (const float*)d_in[2];
    const float* bm1 = (const float*)d_in[3];
    const float* wm2 = (const float*)d_in[4];
    const float* bm2 = (const float*)d_in[5];
    const float* wu1 = (const float*)d_in[6];
    const float* bu1 = (const float*)d_in[7];
    const float* wu2 = (const float*)d_in[8];
    const float* bu2 = (const float*)d_in[9];
    float* out = (float*)d_out;

    int n = in_sizes[0] / DIM;     // 50000
    int e = in_sizes[1] / 2;       // 600000

    const int SMEM_BYTES = (2 * DIM * DIM + BM * LDT + BM) * (int)sizeof(float);
    cudaFuncSetAttribute(hmp_msg_kernel, cudaFuncAttributeMaxDynamicSharedMemorySize, SMEM_BYTES);
    cudaFuncSetAttribute(hmp_upd_kernel, cudaFuncAttributeMaxDynamicSharedMemorySize, SMEM_BYTES);

    int gblocks = (n + BM - 1) / BM;

    hmp_zero_kernel<<<512, 256>>>(n);
    hmp_msg_kernel<<<gblocks, 256, SMEM_BYTES>>>(x, wm1, bm1, wm2, bm2, n);

    long long sthreads = (long long)e * 32;
    int sblocks = (int)((sthreads + 255) / 256);
    hmp_scatter_kernel<<<sblocks, 256>>>(ei, ei + e, e);

    hmp_upd_kernel<<<gblocks, 256, SMEM_BYTES>>>(wu1, bu1, wu2, bu2, out, n);
}

// round 12
// speedup vs baseline: 1.3560x; 1.3560x over previous
#include <cuda_runtime.h>
#include <math.h>

#define DIM 128
#define BM 128
#define LDT 132   // padded row stride; 4*LDT % 32 == 16 -> ty-halves bank-disjoint
#define MAXN 50000

typedef unsigned long long u64;

// Scratch (module-load allocated, not counted against kernel_launch)
__device__ float g_msg[(size_t)MAXN * DIM];
__device__ float g_sum[(size_t)MAXN * DIM];
__device__ int   g_cnt[MAXN];

// ---------------------------------------------------------------------------
// f32x2 packed-FMA helpers (Blackwell FFMA2)
// ---------------------------------------------------------------------------
__device__ __forceinline__ u64 splat2(float a) {
    u64 d; asm("mov.b64 %0, {%1, %1};" : "=l"(d) : "f"(a)); return d;
}
__device__ __forceinline__ void fma2(u64& d, u64 a, u64 b) {
    asm("fma.rn.f32x2 %0, %1, %2, %0;" : "+l"(d) : "l"(a), "l"(b));
}
__device__ __forceinline__ float2 unpack2(u64 d) {
    float2 r; asm("mov.b64 {%0, %1}, %2;" : "=f"(r.x), "=f"(r.y) : "l"(d)); return r;
}

// ---------------------------------------------------------------------------
// Zero the aggregation buffers
// ---------------------------------------------------------------------------
__global__ void hmp_zero_kernel(int n) {
    int stride = gridDim.x * blockDim.x;
    int tid = blockIdx.x * blockDim.x + threadIdx.x;
    float4* s4 = reinterpret_cast<float4*>(g_sum);
    int tot4 = n * (DIM / 4);
    for (int i = tid; i < tot4; i += stride) s4[i] = make_float4(0.f, 0.f, 0.f, 0.f);
    for (int i = tid; i < n; i += stride) g_cnt[i] = 0;
}

// ---------------------------------------------------------------------------
// GEMM stage with packed f32x2 FMA.
// 256 threads as 16x16; thread (ty,tx) owns rows {ty*4+c, 64+ty*4+c} (c=0..3)
// and packed col-pairs tx*8 .. tx*8+7. acc pre-initialized with bias pairs.
// ---------------------------------------------------------------------------
__device__ __forceinline__ void gemm2_stage(const float* __restrict__ sT,
                                            const float* __restrict__ sW,
                                            const int roff[8], int tx,
                                            u64 acc[8][4]) {
#pragma unroll 8
    for (int k = 0; k < DIM; ++k) {
        const ulonglong2* wp =
            reinterpret_cast<const ulonglong2*>(sW + k * DIM + tx * 8);
        ulonglong2 w0 = wp[0];
        ulonglong2 w1 = wp[1];
#pragma unroll
        for (int i = 0; i < 8; ++i) {
            u64 aa = splat2(sT[roff[i] + k]);
            fma2(acc[i][0], aa, w0.x);
            fma2(acc[i][1], aa, w0.y);
            fma2(acc[i][2], aa, w1.x);
            fma2(acc[i][3], aa, w1.y);
        }
    }
}

// ---------------------------------------------------------------------------
// Per-node message MLP: g_msg = relu(logmap0(x) @ W1 + b1) @ W2 + b2
// ---------------------------------------------------------------------------
__global__ __launch_bounds__(256, 1) void hmp_msg_kernel(
    const float* __restrict__ x,
    const float* __restrict__ w1, const float* __restrict__ b1,
    const float* __restrict__ w2, const float* __restrict__ b2, int n)
{
    extern __shared__ float smem[];
    float* sW1  = smem;
    float* sW2  = smem + DIM * DIM;
    float* sT   = smem + 2 * DIM * DIM;
    float* sRow = sT + BM * LDT;

    int tid = threadIdx.x;
    int m0 = blockIdx.x * BM;
    int rows = n - m0; if (rows > BM) rows = BM;

    for (int i = tid; i < DIM * DIM; i += 256) { sW1[i] = w1[i]; sW2[i] = w2[i]; }

    // logmap0 row scale: artanh(clip(||x||)) / clip(||x||)
    int warp = tid >> 5, lane = tid & 31;
#pragma unroll
    for (int r = 0; r < 16; ++r) {
        int m = warp * 16 + r;
        float p = 0.f;
        if (m < rows) {
            float4 v = reinterpret_cast<const float4*>(x + (size_t)(m0 + m) * DIM)[lane];
            p = v.x * v.x + v.y * v.y + v.z * v.z + v.w * v.w;
        }
#pragma unroll
        for (int o = 16; o; o >>= 1) p += __shfl_xor_sync(0xffffffffu, p, o);
        if (lane == 0) {
            float nrm = sqrtf(p);
            float nc = fminf(fmaxf(nrm, 1e-8f), 1.f - 1e-5f);
            sRow[m] = (m < rows) ? (atanhf(nc) / nc) : 0.f;
        }
    }
    __syncthreads();

    // load tile, scaled (row-major, float4)
    for (int i = tid; i < BM * (DIM / 4); i += 256) {
        int m = i >> 5, q = i & 31;
        float4 v = make_float4(0.f, 0.f, 0.f, 0.f);
        if (m < rows) v = reinterpret_cast<const float4*>(x + (size_t)(m0 + m) * DIM)[q];
        float s = sRow[m];
        v.x *= s; v.y *= s; v.z *= s; v.w *= s;
        reinterpret_cast<float4*>(sT + m * LDT)[q] = v;
    }
    __syncthreads();

    int tx = tid & 15, ty = tid >> 4;
    int roff[8];
#pragma unroll
    for (int i = 0; i < 8; ++i) roff[i] = (ty * 4 + (i & 3) + (i >> 2) * 64) * LDT;

    u64 acc[8][4];
    {
        const u64* bb = reinterpret_cast<const u64*>(b1) + tx * 4;
        u64 c0 = bb[0], c1 = bb[1], c2 = bb[2], c3 = bb[3];
#pragma unroll
        for (int i = 0; i < 8; ++i) { acc[i][0] = c0; acc[i][1] = c1; acc[i][2] = c2; acc[i][3] = c3; }
    }
    gemm2_stage(sT, sW1, roff, tx, acc);
    __syncthreads();   // all stage-1 reads done before overwrite

    // relu writeback to sT
#pragma unroll
    for (int i = 0; i < 8; ++i) {
        float2 v0 = unpack2(acc[i][0]);
        float2 v1 = unpack2(acc[i][1]);
        float2 v2 = unpack2(acc[i][2]);
        float2 v3 = unpack2(acc[i][3]);
        float4* dst = reinterpret_cast<float4*>(sT + roff[i] + tx * 8);
        dst[0] = make_float4(fmaxf(v0.x, 0.f), fmaxf(v0.y, 0.f), fmaxf(v1.x, 0.f), fmaxf(v1.y, 0.f));
        dst[1] = make_float4(fmaxf(v2.x, 0.f), fmaxf(v2.y, 0.f), fmaxf(v3.x, 0.f), fmaxf(v3.y, 0.f));
    }
    __syncthreads();

    {
        const u64* bb = reinterpret_cast<const u64*>(b2) + tx * 4;
        u64 c0 = bb[0], c1 = bb[1], c2 = bb[2], c3 = bb[3];
#pragma unroll
        for (int i = 0; i < 8; ++i) { acc[i][0] = c0; acc[i][1] = c1; acc[i][2] = c2; acc[i][3] = c3; }
    }
    gemm2_stage(sT, sW2, roff, tx, acc);

#pragma unroll
    for (int i = 0; i < 8; ++i) {
        int m = ty * 4 + (i & 3) + (i >> 2) * 64;
        if (m < rows) {
            float2 v0 = unpack2(acc[i][0]);
            float2 v1 = unpack2(acc[i][1]);
            float2 v2 = unpack2(acc[i][2]);
            float2 v3 = unpack2(acc[i][3]);
            float4* dst = reinterpret_cast<float4*>(g_msg + (size_t)(m0 + m) * DIM + tx * 8);
            dst[0] = make_float4(v0.x, v0.y, v1.x, v1.y);
            dst[1] = make_float4(v2.x, v2.y, v3.x, v3.y);
        }
    }
}

// ---------------------------------------------------------------------------
// Edge scatter: g_sum[row] += g_msg[col]; g_cnt[row] += 1  (warp per edge)
// ---------------------------------------------------------------------------
__global__ void hmp_scatter_kernel(const int* __restrict__ rows,
                                   const int* __restrict__ cols, int e)
{
    int idx = blockIdx.x * blockDim.x + threadIdx.x;
    int ed = idx >> 5;
    int lane = idx & 31;
    if (ed >= e) return;
    int r = __ldg(rows + ed);
    int c = __ldg(cols + ed);
    float4 v = reinterpret_cast<const float4*>(g_msg + (size_t)c * DIM)[lane];
    float* dst = g_sum + (size_t)r * DIM + lane * 4;
    atomicAdd(dst + 0, v.x);
    atomicAdd(dst + 1, v.y);
    atomicAdd(dst + 2, v.z);
    atomicAdd(dst + 3, v.w);
    if (lane == 0) atomicAdd(g_cnt + r, 1);
}

// ---------------------------------------------------------------------------
// Update MLP + expmap0:
// out = expmap0( relu( (g_sum/(cnt+eps)) @ Wu1 + bu1 ) @ Wu2 + bu2 )
// ---------------------------------------------------------------------------
__global__ __launch_bounds__(256, 1) void hmp_upd_kernel(
    const float* __restrict__ w1, const float* __restrict__ b1,
    const float* __restrict__ w2, const float* __restrict__ b2,
    float* __restrict__ out, int n)
{
    extern __shared__ float smem[];
    float* sW1  = smem;
    float* sW2  = smem + DIM * DIM;
    float* sT   = smem + 2 * DIM * DIM;
    float* sRow = sT + BM * LDT;

    int tid = threadIdx.x;
    int m0 = blockIdx.x * BM;
    int rows = n - m0; if (rows > BM) rows = BM;

    for (int i = tid; i < DIM * DIM; i += 256) { sW1[i] = w1[i]; sW2[i] = w2[i]; }

    if (tid < BM) {
        float inv = 0.f;
        if (tid < rows) inv = 1.f / ((float)g_cnt[m0 + tid] + 1e-8f);
        sRow[tid] = inv;
    }
    __syncthreads();

    for (int i = tid; i < BM * (DIM / 4); i += 256) {
        int m = i >> 5, q = i & 31;
        float4 v = make_float4(0.f, 0.f, 0.f, 0.f);
        if (m < rows) v = reinterpret_cast<const float4*>(g_sum + (size_t)(m0 + m) * DIM)[q];
        float s = sRow[m];
        v.x *= s; v.y *= s; v.z *= s; v.w *= s;
        reinterpret_cast<float4*>(sT + m * LDT)[q] = v;
    }
    __syncthreads();

    int tx = tid & 15, ty = tid >> 4;
    int roff[8];
#pragma unroll
    for (int i = 0; i < 8; ++i) roff[i] = (ty * 4 + (i & 3) + (i >> 2) * 64) * LDT;

    u64 acc[8][4];
    {
        const u64* bb = reinterpret_cast<const u64*>(b1) + tx * 4;
        u64 c0 = bb[0], c1 = bb[1], c2 = bb[2], c3 = bb[3];
#pragma unroll
        for (int i = 0; i < 8; ++i) { acc[i][0] = c0; acc[i][1] = c1; acc[i][2] = c2; acc[i][3] = c3; }
    }
    gemm2_stage(sT, sW1, roff, tx, acc);
    __syncthreads();

#pragma unroll
    for (int i = 0; i < 8; ++i) {
        float2 v0 = unpack2(acc[i][0]);
        float2 v1 = unpack2(acc[i][1]);
        float2 v2 = unpack2(acc[i][2]);
        float2 v3 = unpack2(acc[i][3]);
        float4* dst = reinterpret_cast<float4*>(sT + roff[i] + tx * 8);
        dst[0] = make_float4(fmaxf(v0.x, 0.f), fmaxf(v0.y, 0.f), fmaxf(v1.x, 0.f), fmaxf(v1.y, 0.f));
        dst[1] = make_float4(fmaxf(v2.x, 0.f), fmaxf(v2.y, 0.f), fmaxf(v3.x, 0.f), fmaxf(v3.y, 0.f));
    }
    __syncthreads();

    {
        const u64* bb = reinterpret_cast<const u64*>(b2) + tx * 4;
        u64 c0 = bb[0], c1 = bb[1], c2 = bb[2], c3 = bb[3];
#pragma unroll
        for (int i = 0; i < 8; ++i) { acc[i][0] = c0; acc[i][1] = c1; acc[i][2] = c2; acc[i][3] = c3; }
    }
    gemm2_stage(sT, sW2, roff, tx, acc);

    // expmap0: row norm reduced across the 16 tx lanes (shfl, no smem)
    float v[8][8];
    float scl[8];
#pragma unroll
    for (int i = 0; i < 8; ++i) {
        float2 v0 = unpack2(acc[i][0]);
        float2 v1 = unpack2(acc[i][1]);
        float2 v2 = unpack2(acc[i][2]);
        float2 v3 = unpack2(acc[i][3]);
        v[i][0] = v0.x; v[i][1] = v0.y; v[i][2] = v1.x; v[i][3] = v1.y;
        v[i][4] = v2.x; v[i][5] = v2.y; v[i][6] = v3.x; v[i][7] = v3.y;
        float s = 0.f;
#pragma unroll
        for (int j = 0; j < 8; ++j) s += v[i][j] * v[i][j];
        s += __shfl_xor_sync(0xffffffffu, s, 1);
        s += __shfl_xor_sync(0xffffffffu, s, 2);
        s += __shfl_xor_sync(0xffffffffu, s, 4);
        s += __shfl_xor_sync(0xffffffffu, s, 8);
        float nrm = sqrtf(s);
        float nc = fmaxf(nrm, 1e-8f);
        scl[i] = tanhf(nc) / nc;
    }

#pragma unroll
    for (int i = 0; i < 8; ++i) {
        int m = ty * 4 + (i & 3) + (i >> 2) * 64;
        if (m < rows) {
            float s = scl[i];
            float4* dst = reinterpret_cast<float4*>(out + (size_t)(m0 + m) * DIM + tx * 8);
            dst[0] = make_float4(v[i][0] * s, v[i][1] * s, v[i][2] * s, v[i][3] * s);
            dst[1] = make_float4(v[i][4] * s, v[i][5] * s, v[i][6] * s, v[i][7] * s);
        }
    }
}

// ---------------------------------------------------------------------------
extern "C" void kernel_launch(void* const* d_in, const int* in_sizes, int n_in,
                              void* d_out, int out_size) {
    const float* x   = (const float*)d_in[0];
    const int*   ei  = (const int*)d_in[1];
    const float* wm1 = (const float*)d_in[2];
    const float* bm1 = (const float*)d_in[3];
    const float* wm2 = (const float*)d_in[4];
    const float* bm2 = (const float*)d_in[5];
    const float* wu1 = (const float*)d_in[6];
    const float* bu1 = (const float*)d_in[7];
    const float* wu2 = (const float*)d_in[8];
    const float* bu2 = (const float*)d_in[9];
    float* out = (float*)d_out;

    int n = in_sizes[0] / DIM;     // 50000
    int e = in_sizes[1] / 2;       // 600000

    const int SMEM_BYTES = (2 * DIM * DIM + BM * LDT + BM) * (int)sizeof(float);
    cudaFuncSetAttribute(hmp_msg_kernel, cudaFuncAttributeMaxDynamicSharedMemorySize, SMEM_BYTES);
    cudaFuncSetAttribute(hmp_upd_kernel, cudaFuncAttributeMaxDynamicSharedMemorySize, SMEM_BYTES);

    int gblocks = (n + BM - 1) / BM;

    hmp_zero_kernel<<<512, 256>>>(n);
    hmp_msg_kernel<<<gblocks, 256, SMEM_BYTES>>>(x, wm1, bm1, wm2, bm2, n);

    long long sthreads = (long long)e * 32;
    int sblocks = (int)((sthreads + 255) / 256);
    hmp_scatter_kernel<<<sblocks, 256>>>(ei, ei + e, e);

    hmp_upd_kernel<<<gblocks, 256, SMEM_BYTES>>>(wu1, bu1, wu2, bu2, out, n);
}

// round 13
// speedup vs baseline: 1.3609x; 1.0036x over previous
#include <cuda_runtime.h>
#include <math.h>

#define DIM 128
#define BM 128
#define LDT 132   // padded row stride; 4*LDT % 32 == 16 -> ty-halves bank-disjoint
#define MAXN 50000

typedef unsigned long long u64;

// Scratch (module-load allocated, not counted against kernel_launch)
__device__ float g_msg[(size_t)MAXN * DIM];
__device__ float g_sum[(size_t)MAXN * DIM];
__device__ int   g_cnt[MAXN];

// ---------------------------------------------------------------------------
// f32x2 packed-FMA helpers (Blackwell FFMA2)
// ---------------------------------------------------------------------------
__device__ __forceinline__ u64 splat2(float a) {
    u64 d; asm("mov.b64 %0, {%1, %1};" : "=l"(d) : "f"(a)); return d;
}
__device__ __forceinline__ void fma2(u64& d, u64 a, u64 b) {
    asm("fma.rn.f32x2 %0, %1, %2, %0;" : "+l"(d) : "l"(a), "l"(b));
}
__device__ __forceinline__ float2 unpack2(u64 d) {
    float2 r; asm("mov.b64 {%0, %1}, %2;" : "=f"(r.x), "=f"(r.y) : "l"(d)); return r;
}

// ---------------------------------------------------------------------------
// Zero the aggregation buffers
// ---------------------------------------------------------------------------
__global__ void hmp_zero_kernel(int n) {
    int stride = gridDim.x * blockDim.x;
    int tid = blockIdx.x * blockDim.x + threadIdx.x;
    float4* s4 = reinterpret_cast<float4*>(g_sum);
    int tot4 = n * (DIM / 4);
    for (int i = tid; i < tot4; i += stride) s4[i] = make_float4(0.f, 0.f, 0.f, 0.f);
    for (int i = tid; i < n; i += stride) g_cnt[i] = 0;
}

// ---------------------------------------------------------------------------
// GEMM stage with packed f32x2 FMA.
// 256 threads as 16x16; thread (ty,tx) owns rows {ty*4+c, 64+ty*4+c} (c=0..3)
// and packed col-pairs tx*8 .. tx*8+7. acc pre-initialized with bias pairs.
// ---------------------------------------------------------------------------
__device__ __forceinline__ void gemm2_stage(const float* __restrict__ sT,
                                            const float* __restrict__ sW,
                                            const int roff[8], int tx,
                                            u64 acc[8][4]) {
#pragma unroll 8
    for (int k = 0; k < DIM; ++k) {
        const ulonglong2* wp =
            reinterpret_cast<const ulonglong2*>(sW + k * DIM + tx * 8);
        ulonglong2 w0 = wp[0];
        ulonglong2 w1 = wp[1];
#pragma unroll
        for (int i = 0; i < 8; ++i) {
            u64 aa = splat2(sT[roff[i] + k]);
            fma2(acc[i][0], aa, w0.x);
            fma2(acc[i][1], aa, w0.y);
            fma2(acc[i][2], aa, w1.x);
            fma2(acc[i][3], aa, w1.y);
        }
    }
}

// ---------------------------------------------------------------------------
// Per-node message MLP: g_msg = relu(logmap0(x) @ W1 + b1) @ W2 + b2
// ---------------------------------------------------------------------------
__global__ __launch_bounds__(256, 1) void hmp_msg_kernel(
    const float* __restrict__ x,
    const float* __restrict__ w1, const float* __restrict__ b1,
    const float* __restrict__ w2, const float* __restrict__ b2, int n)
{
    extern __shared__ float smem[];
    float* sW1  = smem;
    float* sW2  = smem + DIM * DIM;
    float* sT   = smem + 2 * DIM * DIM;
    float* sRow = sT + BM * LDT;

    int tid = threadIdx.x;
    int m0 = blockIdx.x * BM;
    int rows = n - m0; if (rows > BM) rows = BM;

    for (int i = tid; i < DIM * DIM; i += 256) { sW1[i] = w1[i]; sW2[i] = w2[i]; }

    // logmap0 row scale: artanh(clip(||x||)) / clip(||x||)
    int warp = tid >> 5, lane = tid & 31;
#pragma unroll
    for (int r = 0; r < 16; ++r) {
        int m = warp * 16 + r;
        float p = 0.f;
        if (m < rows) {
            float4 v = reinterpret_cast<const float4*>(x + (size_t)(m0 + m) * DIM)[lane];
            p = v.x * v.x + v.y * v.y + v.z * v.z + v.w * v.w;
        }
#pragma unroll
        for (int o = 16; o; o >>= 1) p += __shfl_xor_sync(0xffffffffu, p, o);
        if (lane == 0) {
            float nrm = sqrtf(p);
            float nc = fminf(fmaxf(nrm, 1e-8f), 1.f - 1e-5f);
            sRow[m] = (m < rows) ? (atanhf(nc) / nc) : 0.f;
        }
    }
    __syncthreads();

    // load tile, scaled (row-major, float4)
    for (int i = tid; i < BM * (DIM / 4); i += 256) {
        int m = i >> 5, q = i & 31;
        float4 v = make_float4(0.f, 0.f, 0.f, 0.f);
        if (m < rows) v = reinterpret_cast<const float4*>(x + (size_t)(m0 + m) * DIM)[q];
        float s = sRow[m];
        v.x *= s; v.y *= s; v.z *= s; v.w *= s;
        reinterpret_cast<float4*>(sT + m * LDT)[q] = v;
    }
    __syncthreads();

    int tx = tid & 15, ty = tid >> 4;
    int roff[8];
#pragma unroll
    for (int i = 0; i < 8; ++i) roff[i] = (ty * 4 + (i & 3) + (i >> 2) * 64) * LDT;

    u64 acc[8][4];
    {
        const u64* bb = reinterpret_cast<const u64*>(b1) + tx * 4;
        u64 c0 = bb[0], c1 = bb[1], c2 = bb[2], c3 = bb[3];
#pragma unroll
        for (int i = 0; i < 8; ++i) { acc[i][0] = c0; acc[i][1] = c1; acc[i][2] = c2; acc[i][3] = c3; }
    }
    gemm2_stage(sT, sW1, roff, tx, acc);
    __syncthreads();   // all stage-1 reads done before overwrite

    // relu writeback to sT
#pragma unroll
    for (int i = 0; i < 8; ++i) {
        float2 v0 = unpack2(acc[i][0]);
        float2 v1 = unpack2(acc[i][1]);
        float2 v2 = unpack2(acc[i][2]);
        float2 v3 = unpack2(acc[i][3]);
        float4* dst = reinterpret_cast<float4*>(sT + roff[i] + tx * 8);
        dst[0] = make_float4(fmaxf(v0.x, 0.f), fmaxf(v0.y, 0.f), fmaxf(v1.x, 0.f), fmaxf(v1.y, 0.f));
        dst[1] = make_float4(fmaxf(v2.x, 0.f), fmaxf(v2.y, 0.f), fmaxf(v3.x, 0.f), fmaxf(v3.y, 0.f));
    }
    __syncthreads();

    {
        const u64* bb = reinterpret_cast<const u64*>(b2) + tx * 4;
        u64 c0 = bb[0], c1 = bb[1], c2 = bb[2], c3 = bb[3];
#pragma unroll
        for (int i = 0; i < 8; ++i) { acc[i][0] = c0; acc[i][1] = c1; acc[i][2] = c2; acc[i][3] = c3; }
    }
    gemm2_stage(sT, sW2, roff, tx, acc);

#pragma unroll
    for (int i = 0; i < 8; ++i) {
        int m = ty * 4 + (i & 3) + (i >> 2) * 64;
        if (m < rows) {
            float2 v0 = unpack2(acc[i][0]);
            float2 v1 = unpack2(acc[i][1]);
            float2 v2 = unpack2(acc[i][2]);
            float2 v3 = unpack2(acc[i][3]);
            float4* dst = reinterpret_cast<float4*>(g_msg + (size_t)(m0 + m) * DIM + tx * 8);
            dst[0] = make_float4(v0.x, v0.y, v1.x, v1.y);
            dst[1] = make_float4(v2.x, v2.y, v3.x, v3.y);
        }
    }
}

// ---------------------------------------------------------------------------
// Edge scatter: g_sum[row] += g_msg[col]; g_cnt[row] += 1  (warp per edge)
// ---------------------------------------------------------------------------
__global__ void hmp_scatter_kernel(const int* __restrict__ rows,
                                   const int* __restrict__ cols, int e)
{
    int idx = blockIdx.x * blockDim.x + threadIdx.x;
    int ed = idx >> 5;
    int lane = idx & 31;
    if (ed >= e) return;
    int r = __ldg(rows + ed);
    int c = __ldg(cols + ed);
    float4 v = reinterpret_cast<const float4*>(g_msg + (size_t)c * DIM)[lane];
    float* dst = g_sum + (size_t)r * DIM + lane * 4;
    atomicAdd(dst + 0, v.x);
    atomicAdd(dst + 1, v.y);
    atomicAdd(dst + 2, v.z);
    atomicAdd(dst + 3, v.w);
    if (lane == 0) atomicAdd(g_cnt + r, 1);
}

// ---------------------------------------------------------------------------
// Update MLP + expmap0:
// out = expmap0( relu( (g_sum/(cnt+eps)) @ Wu1 + bu1 ) @ Wu2 + bu2 )
// ---------------------------------------------------------------------------
__global__ __launch_bounds__(256, 1) void hmp_upd_kernel(
    const float* __restrict__ w1, const float* __restrict__ b1,
    const float* __restrict__ w2, const float* __restrict__ b2,
    float* __restrict__ out, int n)
{
    extern __shared__ float smem[];
    float* sW1  = smem;
    float* sW2  = smem + DIM * DIM;
    float* sT   = smem + 2 * DIM * DIM;
    float* sRow = sT + BM * LDT;

    int tid = threadIdx.x;
    int m0 = blockIdx.x * BM;
    int rows = n - m0; if (rows > BM) rows = BM;

    for (int i = tid; i < DIM * DIM; i += 256) { sW1[i] = w1[i]; sW2[i] = w2[i]; }

    if (tid < BM) {
        float inv = 0.f;
        if (tid < rows) inv = 1.f / ((float)g_cnt[m0 + tid] + 1e-8f);
        sRow[tid] = inv;
    }
    __syncthreads();

    for (int i = tid; i < BM * (DIM / 4); i += 256) {
        int m = i >> 5, q = i & 31;
        float4 v = make_float4(0.f, 0.f, 0.f, 0.f);
        if (m < rows) v = reinterpret_cast<const float4*>(g_sum + (size_t)(m0 + m) * DIM)[q];
        float s = sRow[m];
        v.x *= s; v.y *= s; v.z *= s; v.w *= s;
        reinterpret_cast<float4*>(sT + m * LDT)[q] = v;
    }
    __syncthreads();

    int tx = tid & 15, ty = tid >> 4;
    int roff[8];
#pragma unroll
    for (int i = 0; i < 8; ++i) roff[i] = (ty * 4 + (i & 3) + (i >> 2) * 64) * LDT;

    u64 acc[8][4];
    {
        const u64* bb = reinterpret_cast<const u64*>(b1) + tx * 4;
        u64 c0 = bb[0], c1 = bb[1], c2 = bb[2], c3 = bb[3];
#pragma unroll
        for (int i = 0; i < 8; ++i) { acc[i][0] = c0; acc[i][1] = c1; acc[i][2] = c2; acc[i][3] = c3; }
    }
    gemm2_stage(sT, sW1, roff, tx, acc);
    __syncthreads();

#pragma unroll
    for (int i = 0; i < 8; ++i) {
        float2 v0 = unpack2(acc[i][0]);
        float2 v1 = unpack2(acc[i][1]);
        float2 v2 = unpack2(acc[i][2]);
        float2 v3 = unpack2(acc[i][3]);
        float4* dst = reinterpret_cast<float4*>(sT + roff[i] + tx * 8);
        dst[0] = make_float4(fmaxf(v0.x, 0.f), fmaxf(v0.y, 0.f), fmaxf(v1.x, 0.f), fmaxf(v1.y, 0.f));
        dst[1] = make_float4(fmaxf(v2.x, 0.f), fmaxf(v2.y, 0.f), fmaxf(v3.x, 0.f), fmaxf(v3.y, 0.f));
    }
    __syncthreads();

    {
        const u64* bb = reinterpret_cast<const u64*>(b2) + tx * 4;
        u64 c0 = bb[0], c1 = bb[1], c2 = bb[2], c3 = bb[3];
#pragma unroll
        for (int i = 0; i < 8; ++i) { acc[i][0] = c0; acc[i][1] = c1; acc[i][2] = c2; acc[i][3] = c3; }
    }
    gemm2_stage(sT, sW2, roff, tx, acc);

    // expmap0: row norm reduced across the 16 tx lanes (shfl, no smem)
    float v[8][8];
    float scl[8];
#pragma unroll
    for (int i = 0; i < 8; ++i) {
        float2 v0 = unpack2(acc[i][0]);
        float2 v1 = unpack2(acc[i][1]);
        float2 v2 = unpack2(acc[i][2]);
        float2 v3 = unpack2(acc[i][3]);
        v[i][0] = v0.x; v[i][1] = v0.y; v[i][2] = v1.x; v[i][3] = v1.y;
        v[i][4] = v2.x; v[i][5] = v2.y; v[i][6] = v3.x; v[i][7] = v3.y;
        float s = 0.f;
#pragma unroll
        for (int j = 0; j < 8; ++j) s += v[i][j] * v[i][j];
        s += __shfl_xor_sync(0xffffffffu, s, 1);
        s += __shfl_xor_sync(0xffffffffu, s, 2);
        s += __shfl_xor_sync(0xffffffffu, s, 4);
        s += __shfl_xor_sync(0xffffffffu, s, 8);
        float nrm = sqrtf(s);
        float nc = fmaxf(nrm, 1e-8f);
        scl[i] = tanhf(nc) / nc;
    }

#pragma unroll
    for (int i = 0; i < 8; ++i) {
        int m = ty * 4 + (i & 3) + (i >> 2) * 64;
        if (m < rows) {
            float s = scl[i];
            float4* dst = reinterpret_cast<float4*>(out + (size_t)(m0 + m) * DIM + tx * 8);
            dst[0] = make_float4(v[i][0] * s, v[i][1] * s, v[i][2] * s, v[i][3] * s);
            dst[1] = make_float4(v[i][4] * s, v[i][5] * s, v[i][6] * s, v[i][7] * s);
        }
    }
}

// ---------------------------------------------------------------------------
extern "C" void kernel_launch(void* const* d_in, const int* in_sizes, int n_in,
                              void* d_out, int out_size) {
    const float* x   = (const float*)d_in[0];
    const int*   ei  = (const int*)d_in[1];
    const float* wm1 = (const float*)d_in[2];
    const float* bm1 = (const float*)d_in[3];
    const float* wm2 = (const float*)d_in[4];
    const float* bm2 = (const float*)d_in[5];
    const float* wu1 = (const float*)d_in[6];
    const float* bu1 = (const float*)d_in[7];
    const float* wu2 = (const float*)d_in[8];
    const float* bu2 = (const float*)d_in[9];
    float* out = (float*)d_out;

    int n = in_sizes[0] / DIM;     // 50000
    int e = in_sizes[1] / 2;       // 600000

    const int SMEM_BYTES = (2 * DIM * DIM + BM * LDT + BM) * (int)sizeof(float);
    cudaFuncSetAttribute(hmp_msg_kernel, cudaFuncAttributeMaxDynamicSharedMemorySize, SMEM_BYTES);
    cudaFuncSetAttribute(hmp_upd_kernel, cudaFuncAttributeMaxDynamicSharedMemorySize, SMEM_BYTES);

    int gblocks = (n + BM - 1) / BM;

    hmp_zero_kernel<<<512, 256>>>(n);
    hmp_msg_kernel<<<gblocks, 256, SMEM_BYTES>>>(x, wm1, bm1, wm2, bm2, n);

    long long sthreads = (long long)e * 32;
    int sblocks = (int)((sthreads + 255) / 256);
    hmp_scatter_kernel<<<sblocks, 256>>>(ei, ei + e, e);

    hmp_upd_kernel<<<gblocks, 256, SMEM_BYTES>>>(wu1, bu1, wu2, bu2, out, n);
}

// round 14
// speedup vs baseline: 1.3612x; 1.0002x over previous
#include <cuda_runtime.h>
#include <math.h>

#define DIM 128
#define BM 128
#define LDT 132   // padded row stride; 4*LDT % 32 == 16 -> ty-halves bank-disjoint
#define MAXN 50000

typedef unsigned long long u64;

// Scratch (module-load allocated, not counted against kernel_launch)
__device__ float g_msg[(size_t)MAXN * DIM];
__device__ float g_sum[(size_t)MAXN * DIM];
__device__ int   g_cnt[MAXN];

// ---------------------------------------------------------------------------
// f32x2 packed-FMA helpers (Blackwell FFMA2)
// ---------------------------------------------------------------------------
__device__ __forceinline__ u64 splat2(float a) {
    u64 d; asm("mov.b64 %0, {%1, %1};" : "=l"(d) : "f"(a)); return d;
}
__device__ __forceinline__ void fma2(u64& d, u64 a, u64 b) {
    asm("fma.rn.f32x2 %0, %1, %2, %0;" : "+l"(d) : "l"(a), "l"(b));
}
__device__ __forceinline__ float2 unpack2(u64 d) {
    float2 r; asm("mov.b64 {%0, %1}, %2;" : "=f"(r.x), "=f"(r.y) : "l"(d)); return r;
}

// ---------------------------------------------------------------------------
// Zero the aggregation buffers
// ---------------------------------------------------------------------------
__global__ void hmp_zero_kernel(int n) {
    int stride = gridDim.x * blockDim.x;
    int tid = blockIdx.x * blockDim.x + threadIdx.x;
    float4* s4 = reinterpret_cast<float4*>(g_sum);
    int tot4 = n * (DIM / 4);
    for (int i = tid; i < tot4; i += stride) s4[i] = make_float4(0.f, 0.f, 0.f, 0.f);
    for (int i = tid; i < n; i += stride) g_cnt[i] = 0;
}

// ---------------------------------------------------------------------------
// GEMM stage with packed f32x2 FMA.
// 256 threads as 16x16; thread (ty,tx) owns rows {ty*4+c, 64+ty*4+c} (c=0..3)
// and packed col-pairs tx*8 .. tx*8+7. acc pre-initialized with bias pairs.
// ---------------------------------------------------------------------------
__device__ __forceinline__ void gemm2_stage(const float* __restrict__ sT,
                                            const float* __restrict__ sW,
                                            const int roff[8], int tx,
                                            u64 acc[8][4]) {
#pragma unroll 8
    for (int k = 0; k < DIM; ++k) {
        const ulonglong2* wp =
            reinterpret_cast<const ulonglong2*>(sW + k * DIM + tx * 8);
        ulonglong2 w0 = wp[0];
        ulonglong2 w1 = wp[1];
#pragma unroll
        for (int i = 0; i < 8; ++i) {
            u64 aa = splat2(sT[roff[i] + k]);
            fma2(acc[i][0], aa, w0.x);
            fma2(acc[i][1], aa, w0.y);
            fma2(acc[i][2], aa, w1.x);
            fma2(acc[i][3], aa, w1.y);
        }
    }
}

// ---------------------------------------------------------------------------
// Per-node message MLP: g_msg = relu(logmap0(x) @ W1 + b1) @ W2 + b2
// ---------------------------------------------------------------------------
__global__ __launch_bounds__(256, 1) void hmp_msg_kernel(
    const float* __restrict__ x,
    const float* __restrict__ w1, const float* __restrict__ b1,
    const float* __restrict__ w2, const float* __restrict__ b2, int n)
{
    extern __shared__ float smem[];
    float* sW1  = smem;
    float* sW2  = smem + DIM * DIM;
    float* sT   = smem + 2 * DIM * DIM;
    float* sRow = sT + BM * LDT;

    int tid = threadIdx.x;
    int m0 = blockIdx.x * BM;
    int rows = n - m0; if (rows > BM) rows = BM;

    for (int i = tid; i < DIM * DIM; i += 256) { sW1[i] = w1[i]; sW2[i] = w2[i]; }

    // logmap0 row scale: artanh(clip(||x||)) / clip(||x||)
    int warp = tid >> 5, lane = tid & 31;
#pragma unroll
    for (int r = 0; r < 16; ++r) {
        int m = warp * 16 + r;
        float p = 0.f;
        if (m < rows) {
            float4 v = reinterpret_cast<const float4*>(x + (size_t)(m0 + m) * DIM)[lane];
            p = v.x * v.x + v.y * v.y + v.z * v.z + v.w * v.w;
        }
#pragma unroll
        for (int o = 16; o; o >>= 1) p += __shfl_xor_sync(0xffffffffu, p, o);
        if (lane == 0) {
            float nrm = sqrtf(p);
            float nc = fminf(fmaxf(nrm, 1e-8f), 1.f - 1e-5f);
            sRow[m] = (m < rows) ? (atanhf(nc) / nc) : 0.f;
        }
    }
    __syncthreads();

    // load tile, scaled (row-major, float4)
    for (int i = tid; i < BM * (DIM / 4); i += 256) {
        int m = i >> 5, q = i & 31;
        float4 v = make_float4(0.f, 0.f, 0.f, 0.f);
        if (m < rows) v = reinterpret_cast<const float4*>(x + (size_t)(m0 + m) * DIM)[q];
        float s = sRow[m];
        v.x *= s; v.y *= s; v.z *= s; v.w *= s;
        reinterpret_cast<float4*>(sT + m * LDT)[q] = v;
    }
    __syncthreads();

    int tx = tid & 15, ty = tid >> 4;
    int roff[8];
#pragma unroll
    for (int i = 0; i < 8; ++i) roff[i] = (ty * 4 + (i & 3) + (i >> 2) * 64) * LDT;

    u64 acc[8][4];
    {
        const u64* bb = reinterpret_cast<const u64*>(b1) + tx * 4;
        u64 c0 = bb[0], c1 = bb[1], c2 = bb[2], c3 = bb[3];
#pragma unroll
        for (int i = 0; i < 8; ++i) { acc[i][0] = c0; acc[i][1] = c1; acc[i][2] = c2; acc[i][3] = c3; }
    }
    gemm2_stage(sT, sW1, roff, tx, acc);
    __syncthreads();   // all stage-1 reads done before overwrite

    // relu writeback to sT
#pragma unroll
    for (int i = 0; i < 8; ++i) {
        float2 v0 = unpack2(acc[i][0]);
        float2 v1 = unpack2(acc[i][1]);
        float2 v2 = unpack2(acc[i][2]);
        float2 v3 = unpack2(acc[i][3]);
        float4* dst = reinterpret_cast<float4*>(sT + roff[i] + tx * 8);
        dst[0] = make_float4(fmaxf(v0.x, 0.f), fmaxf(v0.y, 0.f), fmaxf(v1.x, 0.f), fmaxf(v1.y, 0.f));
        dst[1] = make_float4(fmaxf(v2.x, 0.f), fmaxf(v2.y, 0.f), fmaxf(v3.x, 0.f), fmaxf(v3.y, 0.f));
    }
    __syncthreads();

    {
        const u64* bb = reinterpret_cast<const u64*>(b2) + tx * 4;
        u64 c0 = bb[0], c1 = bb[1], c2 = bb[2], c3 = bb[3];
#pragma unroll
        for (int i = 0; i < 8; ++i) { acc[i][0] = c0; acc[i][1] = c1; acc[i][2] = c2; acc[i][3] = c3; }
    }
    gemm2_stage(sT, sW2, roff, tx, acc);

#pragma unroll
    for (int i = 0; i < 8; ++i) {
        int m = ty * 4 + (i & 3) + (i >> 2) * 64;
        if (m < rows) {
            float2 v0 = unpack2(acc[i][0]);
            float2 v1 = unpack2(acc[i][1]);
            float2 v2 = unpack2(acc[i][2]);
            float2 v3 = unpack2(acc[i][3]);
            float4* dst = reinterpret_cast<float4*>(g_msg + (size_t)(m0 + m) * DIM + tx * 8);
            dst[0] = make_float4(v0.x, v0.y, v1.x, v1.y);
            dst[1] = make_float4(v2.x, v2.y, v3.x, v3.y);
        }
    }
}

// ---------------------------------------------------------------------------
// Edge scatter: g_sum[row] += g_msg[col]; g_cnt[row] += 1  (warp per edge)
// ---------------------------------------------------------------------------
__global__ void hmp_scatter_kernel(const int* __restrict__ rows,
                                   const int* __restrict__ cols, int e)
{
    int idx = blockIdx.x * blockDim.x + threadIdx.x;
    int ed = idx >> 5;
    int lane = idx & 31;
    if (ed >= e) return;
    int r = __ldg(rows + ed);
    int c = __ldg(cols + ed);
    float4 v = reinterpret_cast<const float4*>(g_msg + (size_t)c * DIM)[lane];
    float* dst = g_sum + (size_t)r * DIM + lane * 4;
    atomicAdd(dst + 0, v.x);
    atomicAdd(dst + 1, v.y);
    atomicAdd(dst + 2, v.z);
    atomicAdd(dst + 3, v.w);
    if (lane == 0) atomicAdd(g_cnt + r, 1);
}

// ---------------------------------------------------------------------------
// Update MLP + expmap0:
// out = expmap0( relu( (g_sum/(cnt+eps)) @ Wu1 + bu1 ) @ Wu2 + bu2 )
// ---------------------------------------------------------------------------
__global__ __launch_bounds__(256, 1) void hmp_upd_kernel(
    const float* __restrict__ w1, const float* __restrict__ b1,
    const float* __restrict__ w2, const float* __restrict__ b2,
    float* __restrict__ out, int n)
{
    extern __shared__ float smem[];
    float* sW1  = smem;
    float* sW2  = smem + DIM * DIM;
    float* sT   = smem + 2 * DIM * DIM;
    float* sRow = sT + BM * LDT;

    int tid = threadIdx.x;
    int m0 = blockIdx.x * BM;
    int rows = n - m0; if (rows > BM) rows = BM;

    for (int i = tid; i < DIM * DIM; i += 256) { sW1[i] = w1[i]; sW2[i] = w2[i]; }

    if (tid < BM) {
        float inv = 0.f;
        if (tid < rows) inv = 1.f / ((float)g_cnt[m0 + tid] + 1e-8f);
        sRow[tid] = inv;
    }
    __syncthreads();

    for (int i = tid; i < BM * (DIM / 4); i += 256) {
        int m = i >> 5, q = i & 31;
        float4 v = make_float4(0.f, 0.f, 0.f, 0.f);
        if (m < rows) v = reinterpret_cast<const float4*>(g_sum + (size_t)(m0 + m) * DIM)[q];
        float s = sRow[m];
        v.x *= s; v.y *= s; v.z *= s; v.w *= s;
        reinterpret_cast<float4*>(sT + m * LDT)[q] = v;
    }
    __syncthreads();

    int tx = tid & 15, ty = tid >> 4;
    int roff[8];
#pragma unroll
    for (int i = 0; i < 8; ++i) roff[i] = (ty * 4 + (i & 3) + (i >> 2) * 64) * LDT;

    u64 acc[8][4];
    {
        const u64* bb = reinterpret_cast<const u64*>(b1) + tx * 4;
        u64 c0 = bb[0], c1 = bb[1], c2 = bb[2], c3 = bb[3];
#pragma unroll
        for (int i = 0; i < 8; ++i) { acc[i][0] = c0; acc[i][1] = c1; acc[i][2] = c2; acc[i][3] = c3; }
    }
    gemm2_stage(sT, sW1, roff, tx, acc);
    __syncthreads();

#pragma unroll
    for (int i = 0; i < 8; ++i) {
        float2 v0 = unpack2(acc[i][0]);
        float2 v1 = unpack2(acc[i][1]);
        float2 v2 = unpack2(acc[i][2]);
        float2 v3 = unpack2(acc[i][3]);
        float4* dst = reinterpret_cast<float4*>(sT + roff[i] + tx * 8);
        dst[0] = make_float4(fmaxf(v0.x, 0.f), fmaxf(v0.y, 0.f), fmaxf(v1.x, 0.f), fmaxf(v1.y, 0.f));
        dst[1] = make_float4(fmaxf(v2.x, 0.f), fmaxf(v2.y, 0.f), fmaxf(v3.x, 0.f), fmaxf(v3.y, 0.f));
    }
    __syncthreads();

    {
        const u64* bb = reinterpret_cast<const u64*>(b2) + tx * 4;
        u64 c0 = bb[0], c1 = bb[1], c2 = bb[2], c3 = bb[3];
#pragma unroll
        for (int i = 0; i < 8; ++i) { acc[i][0] = c0; acc[i][1] = c1; acc[i][2] = c2; acc[i][3] = c3; }
    }
    gemm2_stage(sT, sW2, roff, tx, acc);

    // expmap0: row norm reduced across the 16 tx lanes (shfl, no smem)
    float v[8][8];
    float scl[8];
#pragma unroll
    for (int i = 0; i < 8; ++i) {
        float2 v0 = unpack2(acc[i][0]);
        float2 v1 = unpack2(acc[i][1]);
        float2 v2 = unpack2(acc[i][2]);
        float2 v3 = unpack2(acc[i][3]);
        v[i][0] = v0.x; v[i][1] = v0.y; v[i][2] = v1.x; v[i][3] = v1.y;
        v[i][4] = v2.x; v[i][5] = v2.y; v[i][6] = v3.x; v[i][7] = v3.y;
        float s = 0.f;
#pragma unroll
        for (int j = 0; j < 8; ++j) s += v[i][j] * v[i][j];
        s += __shfl_xor_sync(0xffffffffu, s, 1);
        s += __shfl_xor_sync(0xffffffffu, s, 2);
        s += __shfl_xor_sync(0xffffffffu, s, 4);
        s += __shfl_xor_sync(0xffffffffu, s, 8);
        float nrm = sqrtf(s);
        float nc = fmaxf(nrm, 1e-8f);
        scl[i] = tanhf(nc) / nc;
    }

#pragma unroll
    for (int i = 0; i < 8; ++i) {
        int m = ty * 4 + (i & 3) + (i >> 2) * 64;
        if (m < rows) {
            float s = scl[i];
            float4* dst = reinterpret_cast<float4*>(out + (size_t)(m0 + m) * DIM + tx * 8);
            dst[0] = make_float4(v[i][0] * s, v[i][1] * s, v[i][2] * s, v[i][3] * s);
            dst[1] = make_float4(v[i][4] * s, v[i][5] * s, v[i][6] * s, v[i][7] * s);
        }
    }
}

// ---------------------------------------------------------------------------
extern "C" void kernel_launch(void* const* d_in, const int* in_sizes, int n_in,
                              void* d_out, int out_size) {
    const float* x   = (const float*)d_in[0];
    const int*   ei  = (const int*)d_in[1];
    const float* wm1 = (const float*)d_in[2];
    const float* bm1 = (const float*)d_in[3];
    const float* wm2 = (const float*)d_in[4];
    const float* bm2 = (const float*)d_in[5];
    const float* wu1 = (const float*)d_in[6];
    const float* bu1 = (const float*)d_in[7];
    const float* wu2 = (const float*)d_in[8];
    const float* bu2 = (const float*)d_in[9];
    float* out = (float*)d_out;

    int n = in_sizes[0] / DIM;     // 50000
    int e = in_sizes[1] / 2;       // 600000

    const int SMEM_BYTES = (2 * DIM * DIM + BM * LDT + BM) * (int)sizeof(float);
    cudaFuncSetAttribute(hmp_msg_kernel, cudaFuncAttributeMaxDynamicSharedMemorySize, SMEM_BYTES);
    cudaFuncSetAttribute(hmp_upd_kernel, cudaFuncAttributeMaxDynamicSharedMemorySize, SMEM_BYTES);

    int gblocks = (n + BM - 1) / BM;

    hmp_zero_kernel<<<512, 256>>>(n);
    hmp_msg_kernel<<<gblocks, 256, SMEM_BYTES>>>(x, wm1, bm1, wm2, bm2, n);

    long long sthreads = (long long)e * 32;
    int sblocks = (int)((sthreads + 255) / 256);
    hmp_scatter_kernel<<<sblocks, 256>>>(ei, ei + e, e);

    hmp_upd_kernel<<<gblocks, 256, SMEM_BYTES>>>(wu1, bu1, wu2, bu2, out, n);
}

// round 15
// speedup vs baseline: 1.6322x; 1.1991x over previous
#include <cuda_runtime.h>
#include <math.h>

#define DIM 128
#define BM 128
#define LDT 132
#define MAXN 50000
#define MAXE 600000

typedef unsigned long long u64;

// Scratch (module-load allocated)
__device__ float g_msg[(size_t)MAXN * DIM];
__device__ float g_sum[(size_t)MAXN * DIM];   // holds per-node MEAN after aggregate
__device__ int   g_cnt[MAXN];
__device__ int   g_off[MAXN];
__device__ int   g_pos[MAXN];
__device__ int   g_srt[MAXE];
__device__ int   g_bsum[256];

// ---------------------------------------------------------------------------
// f32x2 packed-FMA helpers (Blackwell FFMA2)
// ---------------------------------------------------------------------------
__device__ __forceinline__ u64 splat2(float a) {
    u64 d; asm("mov.b64 %0, {%1, %1};" : "=l"(d) : "f"(a)); return d;
}
__device__ __forceinline__ void fma2(u64& d, u64 a, u64 b) {
    asm("fma.rn.f32x2 %0, %1, %2, %0;" : "+l"(d) : "l"(a), "l"(b));
}
__device__ __forceinline__ float2 unpack2(u64 d) {
    float2 r; asm("mov.b64 {%0, %1}, %2;" : "=f"(r.x), "=f"(r.y) : "l"(d)); return r;
}

// ---------------------------------------------------------------------------
// CSR build: zero counts -> histogram -> 3-kernel exclusive scan -> fill
// ---------------------------------------------------------------------------
__global__ void hmp_zero_cnt_kernel(int n) {
    int tid = blockIdx.x * blockDim.x + threadIdx.x;
    int stride = gridDim.x * blockDim.x;
    for (int i = tid; i < n; i += stride) g_cnt[i] = 0;
}

__global__ void hmp_hist_kernel(const int* __restrict__ rows, int e) {
    int tid = blockIdx.x * blockDim.x + threadIdx.x;
    int stride = gridDim.x * blockDim.x;
    for (int i = tid; i < e; i += stride) atomicAdd(&g_cnt[rows[i]], 1);
}

__global__ void hmp_scan_blocks_kernel(int n) {
    __shared__ int wsum[8];
    int tid = threadIdx.x;
    int i = blockIdx.x * 256 + tid;
    int lane = tid & 31, w = tid >> 5;
    int v = (i < n) ? g_cnt[i] : 0;
    int s = v;
#pragma unroll
    for (int o = 1; o < 32; o <<= 1) {
        int t = __shfl_up_sync(0xffffffffu, s, o);
        if (lane >= o) s += t;
    }
    if (lane == 31) wsum[w] = s;
    __syncthreads();
    if (w == 0) {
        int ws = (lane < 8) ? wsum[lane] : 0;
#pragma unroll
        for (int o = 1; o < 8; o <<= 1) {
            int t = __shfl_up_sync(0xffffffffu, ws, o);
            if (lane >= o) ws += t;
        }
        if (lane < 8) wsum[lane] = ws;
    }
    __syncthreads();
    int base = (w > 0) ? wsum[w - 1] : 0;
    int incl = s + base;
    if (i < n) g_off[i] = incl - v;          // exclusive within block
    if (tid == 255) g_bsum[blockIdx.x] = incl;
}

__global__ void hmp_scan_bsum_kernel(int nb) {
    __shared__ int wsum[8];
    int tid = threadIdx.x;
    int lane = tid & 31, w = tid >> 5;
    int v = (tid < nb) ? g_bsum[tid] : 0;
    int s = v;
#pragma unroll
    for (int o = 1; o < 32; o <<= 1) {
        int t = __shfl_up_sync(0xffffffffu, s, o);
        if (lane >= o) s += t;
    }
    if (lane == 31) wsum[w] = s;
    __syncthreads();
    if (w == 0) {
        int ws = (lane < 8) ? wsum[lane] : 0;
#pragma unroll
        for (int o = 1; o < 8; o <<= 1) {
            int t = __shfl_up_sync(0xffffffffu, ws, o);
            if (lane >= o) ws += t;
        }
        if (lane < 8) wsum[lane] = ws;
    }
    __syncthreads();
    int base = (w > 0) ? wsum[w - 1] : 0;
    if (tid < nb) g_bsum[tid] = s + base - v;  // exclusive
}

__global__ void hmp_scan_add_kernel(int n) {
    int i = blockIdx.x * 256 + threadIdx.x;
    if (i < n) {
        int o = g_off[i] + g_bsum[blockIdx.x];
        g_off[i] = o;
        g_pos[i] = o;
    }
}

__global__ void hmp_fill_kernel(const int* __restrict__ rows,
                                const int* __restrict__ cols, int e) {
    int tid = blockIdx.x * blockDim.x + threadIdx.x;
    int stride = gridDim.x * blockDim.x;
    for (int i = tid; i < e; i += stride) {
        int p = atomicAdd(&g_pos[rows[i]], 1);
        g_srt[p] = cols[i];
    }
}

// ---------------------------------------------------------------------------
// Aggregation: warp per dst node, gather g_msg rows, write mean (no atomics)
// ---------------------------------------------------------------------------
__global__ void hmp_aggregate_kernel(int n) {
    int gw = (blockIdx.x * blockDim.x + threadIdx.x) >> 5;
    int lane = threadIdx.x & 31;
    if (gw >= n) return;
    int start = g_off[gw];
    int cnt = g_cnt[gw];
    float4 acc = make_float4(0.f, 0.f, 0.f, 0.f);
    int j = 0;
    for (; j + 4 <= cnt; j += 4) {
        int s0 = __ldg(g_srt + start + j + 0);
        int s1 = __ldg(g_srt + start + j + 1);
        int s2 = __ldg(g_srt + start + j + 2);
        int s3 = __ldg(g_srt + start + j + 3);
        float4 v0 = reinterpret_cast<const float4*>(g_msg + (size_t)s0 * DIM)[lane];
        float4 v1 = reinterpret_cast<const float4*>(g_msg + (size_t)s1 * DIM)[lane];
        float4 v2 = reinterpret_cast<const float4*>(g_msg + (size_t)s2 * DIM)[lane];
        float4 v3 = reinterpret_cast<const float4*>(g_msg + (size_t)s3 * DIM)[lane];
        acc.x += v0.x + v1.x + v2.x + v3.x;
        acc.y += v0.y + v1.y + v2.y + v3.y;
        acc.z += v0.z + v1.z + v2.z + v3.z;
        acc.w += v0.w + v1.w + v2.w + v3.w;
    }
    for (; j < cnt; ++j) {
        int s0 = __ldg(g_srt + start + j);
        float4 v0 = reinterpret_cast<const float4*>(g_msg + (size_t)s0 * DIM)[lane];
        acc.x += v0.x; acc.y += v0.y; acc.z += v0.z; acc.w += v0.w;
    }
    float inv = 1.f / ((float)cnt + 1e-8f);
    acc.x *= inv; acc.y *= inv; acc.z *= inv; acc.w *= inv;
    reinterpret_cast<float4*>(g_sum + (size_t)gw * DIM)[lane] = acc;
}

// ---------------------------------------------------------------------------
// GEMM stage, FFMA2, 512 threads as 16(tx) x 32(ty).
// Thread owns rows {ty*2+c, 64+ty*2+c} (c=0,1), packed col-pairs tx*8..+7.
// a-operand loaded as float4 over k (1 LDS.128 per row per 4 k's).
// ---------------------------------------------------------------------------
__device__ __forceinline__ void gemm2_stage(const float* __restrict__ sT,
                                            const float* __restrict__ sW,
                                            const int roff[4], int tx,
                                            u64 acc[4][4]) {
#pragma unroll 2
    for (int k0 = 0; k0 < DIM; k0 += 4) {
        float a4[4][4];
#pragma unroll
        for (int i = 0; i < 4; ++i)
            *reinterpret_cast<float4*>(a4[i]) =
                *reinterpret_cast<const float4*>(sT + roff[i] + k0);
#pragma unroll
        for (int kk = 0; kk < 4; ++kk) {
            const ulonglong2* wp =
                reinterpret_cast<const ulonglong2*>(sW + (k0 + kk) * DIM + tx * 8);
            ulonglong2 w0 = wp[0];
            ulonglong2 w1 = wp[1];
#pragma unroll
            for (int i = 0; i < 4; ++i) {
                u64 aa = splat2(a4[i][kk]);
                fma2(acc[i][0], aa, w0.x);
                fma2(acc[i][1], aa, w0.y);
                fma2(acc[i][2], aa, w1.x);
                fma2(acc[i][3], aa, w1.y);
            }
        }
    }
}

// ---------------------------------------------------------------------------
// Per-node message MLP: g_msg = relu(logmap0(x) @ W1 + b1) @ W2 + b2
// ---------------------------------------------------------------------------
__global__ __launch_bounds__(512, 1) void hmp_msg_kernel(
    const float* __restrict__ x,
    const float* __restrict__ w1, const float* __restrict__ b1,
    const float* __restrict__ w2, const float* __restrict__ b2, int n)
{
    extern __shared__ float smem[];
    float* sW1  = smem;
    float* sW2  = smem + DIM * DIM;
    float* sT   = smem + 2 * DIM * DIM;
    float* sRow = sT + BM * LDT;

    int tid = threadIdx.x;
    int m0 = blockIdx.x * BM;
    int rows = n - m0; if (rows > BM) rows = BM;

    for (int i = tid; i < DIM * DIM; i += 512) { sW1[i] = w1[i]; sW2[i] = w2[i]; }

    // logmap0 row scale: artanh(clip(||x||)) / clip(||x||). 16 warps x 8 rows.
    int warp = tid >> 5, lane = tid & 31;
#pragma unroll
    for (int r = 0; r < 8; ++r) {
        int m = warp * 8 + r;
        float p = 0.f;
        if (m < rows) {
            float4 v = reinterpret_cast<const float4*>(x + (size_t)(m0 + m) * DIM)[lane];
            p = v.x * v.x + v.y * v.y + v.z * v.z + v.w * v.w;
        }
#pragma unroll
        for (int o = 16; o; o >>= 1) p += __shfl_xor_sync(0xffffffffu, p, o);
        if (lane == 0) {
            float nrm = sqrtf(p);
            float nc = fminf(fmaxf(nrm, 1e-8f), 1.f - 1e-5f);
            sRow[m] = (m < rows) ? (atanhf(nc) / nc) : 0.f;
        }
    }
    __syncthreads();

    for (int i = tid; i < BM * (DIM / 4); i += 512) {
        int m = i >> 5, q = i & 31;
        float4 v = make_float4(0.f, 0.f, 0.f, 0.f);
        if (m < rows) v = reinterpret_cast<const float4*>(x + (size_t)(m0 + m) * DIM)[q];
        float s = sRow[m];
        v.x *= s; v.y *= s; v.z *= s; v.w *= s;
        reinterpret_cast<float4*>(sT + m * LDT)[q] = v;
    }
    __syncthreads();

    int tx = tid & 15, ty = tid >> 4;
    int roff[4];
#pragma unroll
    for (int i = 0; i < 4; ++i) roff[i] = (ty * 2 + (i & 1) + (i >> 1) * 64) * LDT;

    u64 acc[4][4];
    {
        const u64* bb = reinterpret_cast<const u64*>(b1) + tx * 4;
        u64 c0 = bb[0], c1 = bb[1], c2 = bb[2], c3 = bb[3];
#pragma unroll
        for (int i = 0; i < 4; ++i) { acc[i][0] = c0; acc[i][1] = c1; acc[i][2] = c2; acc[i][3] = c3; }
    }
    gemm2_stage(sT, sW1, roff, tx, acc);
    __syncthreads();

#pragma unroll
    for (int i = 0; i < 4; ++i) {
        float2 v0 = unpack2(acc[i][0]);
        float2 v1 = unpack2(acc[i][1]);
        float2 v2 = unpack2(acc[i][2]);
        float2 v3 = unpack2(acc[i][3]);
        float4* dst = reinterpret_cast<float4*>(sT + roff[i] + tx * 8);
        dst[0] = make_float4(fmaxf(v0.x, 0.f), fmaxf(v0.y, 0.f), fmaxf(v1.x, 0.f), fmaxf(v1.y, 0.f));
        dst[1] = make_float4(fmaxf(v2.x, 0.f), fmaxf(v2.y, 0.f), fmaxf(v3.x, 0.f), fmaxf(v3.y, 0.f));
    }
    __syncthreads();

    {
        const u64* bb = reinterpret_cast<const u64*>(b2) + tx * 4;
        u64 c0 = bb[0], c1 = bb[1], c2 = bb[2], c3 = bb[3];
#pragma unroll
        for (int i = 0; i < 4; ++i) { acc[i][0] = c0; acc[i][1] = c1; acc[i][2] = c2; acc[i][3] = c3; }
    }
    gemm2_stage(sT, sW2, roff, tx, acc);

#pragma unroll
    for (int i = 0; i < 4; ++i) {
        int m = ty * 2 + (i & 1) + (i >> 1) * 64;
        if (m < rows) {
            float2 v0 = unpack2(acc[i][0]);
            float2 v1 = unpack2(acc[i][1]);
            float2 v2 = unpack2(acc[i][2]);
            float2 v3 = unpack2(acc[i][3]);
            float4* dst = reinterpret_cast<float4*>(g_msg + (size_t)(m0 + m) * DIM + tx * 8);
            dst[0] = make_float4(v0.x, v0.y, v1.x, v1.y);
            dst[1] = make_float4(v2.x, v2.y, v3.x, v3.y);
        }
    }
}

// ---------------------------------------------------------------------------
// Update MLP + expmap0 (g_sum already holds the mean)
// ---------------------------------------------------------------------------
__global__ __launch_bounds__(512, 1) void hmp_upd_kernel(
    const float* __restrict__ w1, const float* __restrict__ b1,
    const float* __restrict__ w2, const float* __restrict__ b2,
    float* __restrict__ out, int n)
{
    extern __shared__ float smem[];
    float* sW1  = smem;
    float* sW2  = smem + DIM * DIM;
    float* sT   = smem + 2 * DIM * DIM;

    int tid = threadIdx.x;
    int m0 = blockIdx.x * BM;
    int rows = n - m0; if (rows > BM) rows = BM;

    for (int i = tid; i < DIM * DIM; i += 512) { sW1[i] = w1[i]; sW2[i] = w2[i]; }

    for (int i = tid; i < BM * (DIM / 4); i += 512) {
        int m = i >> 5, q = i & 31;
        float4 v = make_float4(0.f, 0.f, 0.f, 0.f);
        if (m < rows) v = reinterpret_cast<const float4*>(g_sum + (size_t)(m0 + m) * DIM)[q];
        reinterpret_cast<float4*>(sT + m * LDT)[q] = v;
    }
    __syncthreads();

    int tx = tid & 15, ty = tid >> 4;
    int roff[4];
#pragma unroll
    for (int i = 0; i < 4; ++i) roff[i] = (ty * 2 + (i & 1) + (i >> 1) * 64) * LDT;

    u64 acc[4][4];
    {
        const u64* bb = reinterpret_cast<const u64*>(b1) + tx * 4;
        u64 c0 = bb[0], c1 = bb[1], c2 = bb[2], c3 = bb[3];
#pragma unroll
        for (int i = 0; i < 4; ++i) { acc[i][0] = c0; acc[i][1] = c1; acc[i][2] = c2; acc[i][3] = c3; }
    }
    gemm2_stage(sT, sW1, roff, tx, acc);
    __syncthreads();

#pragma unroll
    for (int i = 0; i < 4; ++i) {
        float2 v0 = unpack2(acc[i][0]);
        float2 v1 = unpack2(acc[i][1]);
        float2 v2 = unpack2(acc[i][2]);
        float2 v3 = unpack2(acc[i][3]);
        float4* dst = reinterpret_cast<float4*>(sT + roff[i] + tx * 8);
        dst[0] = make_float4(fmaxf(v0.x, 0.f), fmaxf(v0.y, 0.f), fmaxf(v1.x, 0.f), fmaxf(v1.y, 0.f));
        dst[1] = make_float4(fmaxf(v2.x, 0.f), fmaxf(v2.y, 0.f), fmaxf(v3.x, 0.f), fmaxf(v3.y, 0.f));
    }
    __syncthreads();

    {
        const u64* bb = reinterpret_cast<const u64*>(b2) + tx * 4;
        u64 c0 = bb[0], c1 = bb[1], c2 = bb[2], c3 = bb[3];
#pragma unroll
        for (int i = 0; i < 4; ++i) { acc[i][0] = c0; acc[i][1] = c1; acc[i][2] = c2; acc[i][3] = c3; }
    }
    gemm2_stage(sT, sW2, roff, tx, acc);

    // expmap0: row norm reduced across the 16 tx lanes (shfl, no smem)
    float v[4][8];
    float scl[4];
#pragma unroll
    for (int i = 0; i < 4; ++i) {
        float2 v0 = unpack2(acc[i][0]);
        float2 v1 = unpack2(acc[i][1]);
        float2 v2 = unpack2(acc[i][2]);
        float2 v3 = unpack2(acc[i][3]);
        v[i][0] = v0.x; v[i][1] = v0.y; v[i][2] = v1.x; v[i][3] = v1.y;
        v[i][4] = v2.x; v[i][5] = v2.y; v[i][6] = v3.x; v[i][7] = v3.y;
        float s = 0.f;
#pragma unroll
        for (int j = 0; j < 8; ++j) s += v[i][j] * v[i][j];
        s += __shfl_xor_sync(0xffffffffu, s, 1);
        s += __shfl_xor_sync(0xffffffffu, s, 2);
        s += __shfl_xor_sync(0xffffffffu, s, 4);
        s += __shfl_xor_sync(0xffffffffu, s, 8);
        float nrm = sqrtf(s);
        float nc = fmaxf(nrm, 1e-8f);
        scl[i] = tanhf(nc) / nc;
    }

#pragma unroll
    for (int i = 0; i < 4; ++i) {
        int m = ty * 2 + (i & 1) + (i >> 1) * 64;
        if (m < rows) {
            float s = scl[i];
            float4* dst = reinterpret_cast<float4*>(out + (size_t)(m0 + m) * DIM + tx * 8);
            dst[0] = make_float4(v[i][0] * s, v[i][1] * s, v[i][2] * s, v[i][3] * s);
            dst[1] = make_float4(v[i][4] * s, v[i][5] * s, v[i][6] * s, v[i][7] * s);
        }
    }
}

// ---------------------------------------------------------------------------
extern "C" void kernel_launch(void* const* d_in, const int* in_sizes, int n_in,
                              void* d_out, int out_size) {
    const float* x   = (const float*)d_in[0];
    const int*   ei  = (const int*)d_in[1];
    const float* wm1 = (const float*)d_in[2];
    const float* bm1 = (const float*)d_in[3];
    const float* wm2 = (const float*)d_in[4];
    const float* bm2 = (const float*)d_in[5];
    const float* wu1 = (const float*)d_in[6];
    const float* bu1 = (const float*)d_in[7];
    const float* wu2 = (const float*)d_in[8];
    const float* bu2 = (const float*)d_in[9];
    float* out = (float*)d_out;

    int n = in_sizes[0] / DIM;     // 50000
    int e = in_sizes[1] / 2;       // 600000
    const int* rows = ei;
    const int* cols = ei + e;

    const int SMEM_BYTES = (2 * DIM * DIM + BM * LDT + BM) * (int)sizeof(float);
    cudaFuncSetAttribute(hmp_msg_kernel, cudaFuncAttributeMaxDynamicSharedMemorySize, SMEM_BYTES);
    cudaFuncSetAttribute(hmp_upd_kernel, cudaFuncAttributeMaxDynamicSharedMemorySize, SMEM_BYTES);

    int gblocks = (n + BM - 1) / BM;
    int nb = (n + 255) / 256;

    // CSR build
    hmp_zero_cnt_kernel<<<64, 256>>>(n);
    hmp_hist_kernel<<<592, 256>>>(rows, e);
    hmp_scan_blocks_kernel<<<nb, 256>>>(n);
    hmp_scan_bsum_kernel<<<1, 256>>>(nb);
    hmp_scan_add_kernel<<<nb, 256>>>(n);
    hmp_fill_kernel<<<592, 256>>>(rows, cols, e);

    // message MLP (independent of CSR build)
    hmp_msg_kernel<<<gblocks, 512, SMEM_BYTES>>>(x, wm1, bm1, wm2, bm2, n);

    // mean aggregation (needs msg + CSR)
    int ablocks = (n * 32 + 255) / 256;
    hmp_aggregate_kernel<<<ablocks, 256>>>(n);

    // update MLP + expmap0
    hmp_upd_kernel<<<gblocks, 512, SMEM_BYTES>>>(wu1, bu1, wu2, bu2, out, n);
}

// round 16
// speedup vs baseline: 1.6352x; 1.0018x over previous
#include <cuda_runtime.h>
#include <math.h>

#define DIM 128
#define BM 128
#define LDT 132
#define MAXN 50000
#define MAXE 600000

typedef unsigned long long u64;

// Scratch (module-load allocated)
__device__ float g_msg[(size_t)MAXN * DIM];
__device__ float g_sum[(size_t)MAXN * DIM];   // holds per-node MEAN after aggregate
__device__ int   g_cnt[MAXN];
__device__ int   g_off[MAXN];
__device__ int   g_pos[MAXN];
__device__ int   g_srt[MAXE];
__device__ int   g_bsum[256];

// ---------------------------------------------------------------------------
// f32x2 packed-FMA helpers (Blackwell FFMA2)
// ---------------------------------------------------------------------------
__device__ __forceinline__ u64 splat2(float a) {
    u64 d; asm("mov.b64 %0, {%1, %1};" : "=l"(d) : "f"(a)); return d;
}
__device__ __forceinline__ void fma2(u64& d, u64 a, u64 b) {
    asm("fma.rn.f32x2 %0, %1, %2, %0;" : "+l"(d) : "l"(a), "l"(b));
}
__device__ __forceinline__ float2 unpack2(u64 d) {
    float2 r; asm("mov.b64 {%0, %1}, %2;" : "=f"(r.x), "=f"(r.y) : "l"(d)); return r;
}

// ---------------------------------------------------------------------------
// CSR build: zero counts -> histogram -> 3-kernel exclusive scan -> fill
// ---------------------------------------------------------------------------
__global__ void hmp_zero_cnt_kernel(int n) {
    int tid = blockIdx.x * blockDim.x + threadIdx.x;
    int stride = gridDim.x * blockDim.x;
    for (int i = tid; i < n; i += stride) g_cnt[i] = 0;
}

__global__ void hmp_hist_kernel(const int* __restrict__ rows, int e) {
    int tid = blockIdx.x * blockDim.x + threadIdx.x;
    int stride = gridDim.x * blockDim.x;
    for (int i = tid; i < e; i += stride) atomicAdd(&g_cnt[rows[i]], 1);
}

__global__ void hmp_scan_blocks_kernel(int n) {
    __shared__ int wsum[8];
    int tid = threadIdx.x;
    int i = blockIdx.x * 256 + tid;
    int lane = tid & 31, w = tid >> 5;
    int v = (i < n) ? g_cnt[i] : 0;
    int s = v;
#pragma unroll
    for (int o = 1; o < 32; o <<= 1) {
        int t = __shfl_up_sync(0xffffffffu, s, o);
        if (lane >= o) s += t;
    }
    if (lane == 31) wsum[w] = s;
    __syncthreads();
    if (w == 0) {
        int ws = (lane < 8) ? wsum[lane] : 0;
#pragma unroll
        for (int o = 1; o < 8; o <<= 1) {
            int t = __shfl_up_sync(0xffffffffu, ws, o);
            if (lane >= o) ws += t;
        }
        if (lane < 8) wsum[lane] = ws;
    }
    __syncthreads();
    int base = (w > 0) ? wsum[w - 1] : 0;
    int incl = s + base;
    if (i < n) g_off[i] = incl - v;          // exclusive within block
    if (tid == 255) g_bsum[blockIdx.x] = incl;
}

__global__ void hmp_scan_bsum_kernel(int nb) {
    __shared__ int wsum[8];
    int tid = threadIdx.x;
    int lane = tid & 31, w = tid >> 5;
    int v = (tid < nb) ? g_bsum[tid] : 0;
    int s = v;
#pragma unroll
    for (int o = 1; o < 32; o <<= 1) {
        int t = __shfl_up_sync(0xffffffffu, s, o);
        if (lane >= o) s += t;
    }
    if (lane == 31) wsum[w] = s;
    __syncthreads();
    if (w == 0) {
        int ws = (lane < 8) ? wsum[lane] : 0;
#pragma unroll
        for (int o = 1; o < 8; o <<= 1) {
            int t = __shfl_up_sync(0xffffffffu, ws, o);
            if (lane >= o) ws += t;
        }
        if (lane < 8) wsum[lane] = ws;
    }
    __syncthreads();
    int base = (w > 0) ? wsum[w - 1] : 0;
    if (tid < nb) g_bsum[tid] = s + base - v;  // exclusive
}

__global__ void hmp_scan_add_kernel(int n) {
    int i = blockIdx.x * 256 + threadIdx.x;
    if (i < n) {
        int o = g_off[i] + g_bsum[blockIdx.x];
        g_off[i] = o;
        g_pos[i] = o;
    }
}

__global__ void hmp_fill_kernel(const int* __restrict__ rows,
                                const int* __restrict__ cols, int e) {
    int tid = blockIdx.x * blockDim.x + threadIdx.x;
    int stride = gridDim.x * blockDim.x;
    for (int i = tid; i < e; i += stride) {
        int p = atomicAdd(&g_pos[rows[i]], 1);
        g_srt[p] = cols[i];
    }
}

// ---------------------------------------------------------------------------
// Aggregation: warp per dst node, gather g_msg rows, write mean (no atomics)
// ---------------------------------------------------------------------------
__global__ void hmp_aggregate_kernel(int n) {
    int gw = (blockIdx.x * blockDim.x + threadIdx.x) >> 5;
    int lane = threadIdx.x & 31;
    if (gw >= n) return;
    int start = g_off[gw];
    int cnt = g_cnt[gw];
    float4 acc = make_float4(0.f, 0.f, 0.f, 0.f);
    int j = 0;
    for (; j + 4 <= cnt; j += 4) {
        int s0 = __ldg(g_srt + start + j + 0);
        int s1 = __ldg(g_srt + start + j + 1);
        int s2 = __ldg(g_srt + start + j + 2);
        int s3 = __ldg(g_srt + start + j + 3);
        float4 v0 = reinterpret_cast<const float4*>(g_msg + (size_t)s0 * DIM)[lane];
        float4 v1 = reinterpret_cast<const float4*>(g_msg + (size_t)s1 * DIM)[lane];
        float4 v2 = reinterpret_cast<const float4*>(g_msg + (size_t)s2 * DIM)[lane];
        float4 v3 = reinterpret_cast<const float4*>(g_msg + (size_t)s3 * DIM)[lane];
        acc.x += v0.x + v1.x + v2.x + v3.x;
        acc.y += v0.y + v1.y + v2.y + v3.y;
        acc.z += v0.z + v1.z + v2.z + v3.z;
        acc.w += v0.w + v1.w + v2.w + v3.w;
    }
    for (; j < cnt; ++j) {
        int s0 = __ldg(g_srt + start + j);
        float4 v0 = reinterpret_cast<const float4*>(g_msg + (size_t)s0 * DIM)[lane];
        acc.x += v0.x; acc.y += v0.y; acc.z += v0.z; acc.w += v0.w;
    }
    float inv = 1.f / ((float)cnt + 1e-8f);
    acc.x *= inv; acc.y *= inv; acc.z *= inv; acc.w *= inv;
    reinterpret_cast<float4*>(g_sum + (size_t)gw * DIM)[lane] = acc;
}

// ---------------------------------------------------------------------------
// GEMM stage, FFMA2, 512 threads as 16(tx) x 32(ty).
// Thread owns rows {ty*2+c, 64+ty*2+c} (c=0,1), packed col-pairs tx*8..+7.
// a-operand loaded as float4 over k (1 LDS.128 per row per 4 k's).
// ---------------------------------------------------------------------------
__device__ __forceinline__ void gemm2_stage(const float* __restrict__ sT,
                                            const float* __restrict__ sW,
                                            const int roff[4], int tx,
                                            u64 acc[4][4]) {
#pragma unroll 2
    for (int k0 = 0; k0 < DIM; k0 += 4) {
        float a4[4][4];
#pragma unroll
        for (int i = 0; i < 4; ++i)
            *reinterpret_cast<float4*>(a4[i]) =
                *reinterpret_cast<const float4*>(sT + roff[i] + k0);
#pragma unroll
        for (int kk = 0; kk < 4; ++kk) {
            const ulonglong2* wp =
                reinterpret_cast<const ulonglong2*>(sW + (k0 + kk) * DIM + tx * 8);
            ulonglong2 w0 = wp[0];
            ulonglong2 w1 = wp[1];
#pragma unroll
            for (int i = 0; i < 4; ++i) {
                u64 aa = splat2(a4[i][kk]);
                fma2(acc[i][0], aa, w0.x);
                fma2(acc[i][1], aa, w0.y);
                fma2(acc[i][2], aa, w1.x);
                fma2(acc[i][3], aa, w1.y);
            }
        }
    }
}

// ---------------------------------------------------------------------------
// Per-node message MLP: g_msg = relu(logmap0(x) @ W1 + b1) @ W2 + b2
// ---------------------------------------------------------------------------
__global__ __launch_bounds__(512, 1) void hmp_msg_kernel(
    const float* __restrict__ x,
    const float* __restrict__ w1, const float* __restrict__ b1,
    const float* __restrict__ w2, const float* __restrict__ b2, int n)
{
    extern __shared__ float smem[];
    float* sW1  = smem;
    float* sW2  = smem + DIM * DIM;
    float* sT   = smem + 2 * DIM * DIM;
    float* sRow = sT + BM * LDT;

    int tid = threadIdx.x;
    int m0 = blockIdx.x * BM;
    int rows = n - m0; if (rows > BM) rows = BM;

    for (int i = tid; i < DIM * DIM; i += 512) { sW1[i] = w1[i]; sW2[i] = w2[i]; }

    // logmap0 row scale: artanh(clip(||x||)) / clip(||x||). 16 warps x 8 rows.
    int warp = tid >> 5, lane = tid & 31;
#pragma unroll
    for (int r = 0; r < 8; ++r) {
        int m = warp * 8 + r;
        float p = 0.f;
        if (m < rows) {
            float4 v = reinterpret_cast<const float4*>(x + (size_t)(m0 + m) * DIM)[lane];
            p = v.x * v.x + v.y * v.y + v.z * v.z + v.w * v.w;
        }
#pragma unroll
        for (int o = 16; o; o >>= 1) p += __shfl_xor_sync(0xffffffffu, p, o);
        if (lane == 0) {
            float nrm = sqrtf(p);
            float nc = fminf(fmaxf(nrm, 1e-8f), 1.f - 1e-5f);
            sRow[m] = (m < rows) ? (atanhf(nc) / nc) : 0.f;
        }
    }
    __syncthreads();

    for (int i = tid; i < BM * (DIM / 4); i += 512) {
        int m = i >> 5, q = i & 31;
        float4 v = make_float4(0.f, 0.f, 0.f, 0.f);
        if (m < rows) v = reinterpret_cast<const float4*>(x + (size_t)(m0 + m) * DIM)[q];
        float s = sRow[m];
        v.x *= s; v.y *= s; v.z *= s; v.w *= s;
        reinterpret_cast<float4*>(sT + m * LDT)[q] = v;
    }
    __syncthreads();

    int tx = tid & 15, ty = tid >> 4;
    int roff[4];
#pragma unroll
    for (int i = 0; i < 4; ++i) roff[i] = (ty * 2 + (i & 1) + (i >> 1) * 64) * LDT;

    u64 acc[4][4];
    {
        const u64* bb = reinterpret_cast<const u64*>(b1) + tx * 4;
        u64 c0 = bb[0], c1 = bb[1], c2 = bb[2], c3 = bb[3];
#pragma unroll
        for (int i = 0; i < 4; ++i) { acc[i][0] = c0; acc[i][1] = c1; acc[i][2] = c2; acc[i][3] = c3; }
    }
    gemm2_stage(sT, sW1, roff, tx, acc);
    __syncthreads();

#pragma unroll
    for (int i = 0; i < 4; ++i) {
        float2 v0 = unpack2(acc[i][0]);
        float2 v1 = unpack2(acc[i][1]);
        float2 v2 = unpack2(acc[i][2]);
        float2 v3 = unpack2(acc[i][3]);
        float4* dst = reinterpret_cast<float4*>(sT + roff[i] + tx * 8);
        dst[0] = make_float4(fmaxf(v0.x, 0.f), fmaxf(v0.y, 0.f), fmaxf(v1.x, 0.f), fmaxf(v1.y, 0.f));
        dst[1] = make_float4(fmaxf(v2.x, 0.f), fmaxf(v2.y, 0.f), fmaxf(v3.x, 0.f), fmaxf(v3.y, 0.f));
    }
    __syncthreads();

    {
        const u64* bb = reinterpret_cast<const u64*>(b2) + tx * 4;
        u64 c0 = bb[0], c1 = bb[1], c2 = bb[2], c3 = bb[3];
#pragma unroll
        for (int i = 0; i < 4; ++i) { acc[i][0] = c0; acc[i][1] = c1; acc[i][2] = c2; acc[i][3] = c3; }
    }
    gemm2_stage(sT, sW2, roff, tx, acc);

#pragma unroll
    for (int i = 0; i < 4; ++i) {
        int m = ty * 2 + (i & 1) + (i >> 1) * 64;
        if (m < rows) {
            float2 v0 = unpack2(acc[i][0]);
            float2 v1 = unpack2(acc[i][1]);
            float2 v2 = unpack2(acc[i][2]);
            float2 v3 = unpack2(acc[i][3]);
            float4* dst = reinterpret_cast<float4*>(g_msg + (size_t)(m0 + m) * DIM + tx * 8);
            dst[0] = make_float4(v0.x, v0.y, v1.x, v1.y);
            dst[1] = make_float4(v2.x, v2.y, v3.x, v3.y);
        }
    }
}

// ---------------------------------------------------------------------------
// Update MLP + expmap0 (g_sum already holds the mean)
// ---------------------------------------------------------------------------
__global__ __launch_bounds__(512, 1) void hmp_upd_kernel(
    const float* __restrict__ w1, const float* __restrict__ b1,
    const float* __restrict__ w2, const float* __restrict__ b2,
    float* __restrict__ out, int n)
{
    extern __shared__ float smem[];
    float* sW1  = smem;
    float* sW2  = smem + DIM * DIM;
    float* sT   = smem + 2 * DIM * DIM;

    int tid = threadIdx.x;
    int m0 = blockIdx.x * BM;
    int rows = n - m0; if (rows > BM) rows = BM;

    for (int i = tid; i < DIM * DIM; i += 512) { sW1[i] = w1[i]; sW2[i] = w2[i]; }

    for (int i = tid; i < BM * (DIM / 4); i += 512) {
        int m = i >> 5, q = i & 31;
        float4 v = make_float4(0.f, 0.f, 0.f, 0.f);
        if (m < rows) v = reinterpret_cast<const float4*>(g_sum + (size_t)(m0 + m) * DIM)[q];
        reinterpret_cast<float4*>(sT + m * LDT)[q] = v;
    }
    __syncthreads();

    int tx = tid & 15, ty = tid >> 4;
    int roff[4];
#pragma unroll
    for (int i = 0; i < 4; ++i) roff[i] = (ty * 2 + (i & 1) + (i >> 1) * 64) * LDT;

    u64 acc[4][4];
    {
        const u64* bb = reinterpret_cast<const u64*>(b1) + tx * 4;
        u64 c0 = bb[0], c1 = bb[1], c2 = bb[2], c3 = bb[3];
#pragma unroll
        for (int i = 0; i < 4; ++i) { acc[i][0] = c0; acc[i][1] = c1; acc[i][2] = c2; acc[i][3] = c3; }
    }
    gemm2_stage(sT, sW1, roff, tx, acc);
    __syncthreads();

#pragma unroll
    for (int i = 0; i < 4; ++i) {
        float2 v0 = unpack2(acc[i][0]);
        float2 v1 = unpack2(acc[i][1]);
        float2 v2 = unpack2(acc[i][2]);
        float2 v3 = unpack2(acc[i][3]);
        float4* dst = reinterpret_cast<float4*>(sT + roff[i] + tx * 8);
        dst[0] = make_float4(fmaxf(v0.x, 0.f), fmaxf(v0.y, 0.f), fmaxf(v1.x, 0.f), fmaxf(v1.y, 0.f));
        dst[1] = make_float4(fmaxf(v2.x, 0.f), fmaxf(v2.y, 0.f), fmaxf(v3.x, 0.f), fmaxf(v3.y, 0.f));
    }
    __syncthreads();

    {
        const u64* bb = reinterpret_cast<const u64*>(b2) + tx * 4;
        u64 c0 = bb[0], c1 = bb[1], c2 = bb[2], c3 = bb[3];
#pragma unroll
        for (int i = 0; i < 4; ++i) { acc[i][0] = c0; acc[i][1] = c1; acc[i][2] = c2; acc[i][3] = c3; }
    }
    gemm2_stage(sT, sW2, roff, tx, acc);

    // expmap0: row norm reduced across the 16 tx lanes (shfl, no smem)
    float v[4][8];
    float scl[4];
#pragma unroll
    for (int i = 0; i < 4; ++i) {
        float2 v0 = unpack2(acc[i][0]);
        float2 v1 = unpack2(acc[i][1]);
        float2 v2 = unpack2(acc[i][2]);
        float2 v3 = unpack2(acc[i][3]);
        v[i][0] = v0.x; v[i][1] = v0.y; v[i][2] = v1.x; v[i][3] = v1.y;
        v[i][4] = v2.x; v[i][5] = v2.y; v[i][6] = v3.x; v[i][7] = v3.y;
        float s = 0.f;
#pragma unroll
        for (int j = 0; j < 8; ++j) s += v[i][j] * v[i][j];
        s += __shfl_xor_sync(0xffffffffu, s, 1);
        s += __shfl_xor_sync(0xffffffffu, s, 2);
        s += __shfl_xor_sync(0xffffffffu, s, 4);
        s += __shfl_xor_sync(0xffffffffu, s, 8);
        float nrm = sqrtf(s);
        float nc = fmaxf(nrm, 1e-8f);
        scl[i] = tanhf(nc) / nc;
    }

#pragma unroll
    for (int i = 0; i < 4; ++i) {
        int m = ty * 2 + (i & 1) + (i >> 1) * 64;
        if (m < rows) {
            float s = scl[i];
            float4* dst = reinterpret_cast<float4*>(out + (size_t)(m0 + m) * DIM + tx * 8);
            dst[0] = make_float4(v[i][0] * s, v[i][1] * s, v[i][2] * s, v[i][3] * s);
            dst[1] = make_float4(v[i][4] * s, v[i][5] * s, v[i][6] * s, v[i][7] * s);
        }
    }
}

// ---------------------------------------------------------------------------
extern "C" void kernel_launch(void* const* d_in, const int* in_sizes, int n_in,
                              void* d_out, int out_size) {
    const float* x   = (const float*)d_in[0];
    const int*   ei  = (const int*)d_in[1];
    const float* wm1 = (const float*)d_in[2];
    const float* bm1 = (const float*)d_in[3];
    const float* wm2 = (const float*)d_in[4];
    const float* bm2 = (const float*)d_in[5];
    const float* wu1 = (const float*)d_in[6];
    const float* bu1 = (const float*)d_in[7];
    const float* wu2 = (const float*)d_in[8];
    const float* bu2 = (const float*)d_in[9];
    float* out = (float*)d_out;

    int n = in_sizes[0] / DIM;     // 50000
    int e = in_sizes[1] / 2;       // 600000
    const int* rows = ei;
    const int* cols = ei + e;

    const int SMEM_BYTES = (2 * DIM * DIM + BM * LDT + BM) * (int)sizeof(float);
    cudaFuncSetAttribute(hmp_msg_kernel, cudaFuncAttributeMaxDynamicSharedMemorySize, SMEM_BYTES);
    cudaFuncSetAttribute(hmp_upd_kernel, cudaFuncAttributeMaxDynamicSharedMemorySize, SMEM_BYTES);

    int gblocks = (n + BM - 1) / BM;
    int nb = (n + 255) / 256;

    // CSR build
    hmp_zero_cnt_kernel<<<64, 256>>>(n);
    hmp_hist_kernel<<<592, 256>>>(rows, e);
    hmp_scan_blocks_kernel<<<nb, 256>>>(n);
    hmp_scan_bsum_kernel<<<1, 256>>>(nb);
    hmp_scan_add_kernel<<<nb, 256>>>(n);
    hmp_fill_kernel<<<592, 256>>>(rows, cols, e);

    // message MLP (independent of CSR build)
    hmp_msg_kernel<<<gblocks, 512, SMEM_BYTES>>>(x, wm1, bm1, wm2, bm2, n);

    // mean aggregation (needs msg + CSR)
    int ablocks = (n * 32 + 255) / 256;
    hmp_aggregate_kernel<<<ablocks, 256>>>(n);

    // update MLP + expmap0
    hmp_upd_kernel<<<gblocks, 512, SMEM_BYTES>>>(wu1, bu1, wu2, bu2, out, n);
}

// round 17
// speedup vs baseline: 1.6390x; 1.0023x over previous
#include <cuda_runtime.h>
#include <math.h>

#define DIM 128
#define BM 128
#define LDT 132
#define MAXN 50000
#define MAXE 600000

typedef unsigned long long u64;

// Scratch (module-load allocated)
__device__ float g_msg[(size_t)MAXN * DIM];
__device__ float g_sum[(size_t)MAXN * DIM];   // holds per-node MEAN after aggregate
__device__ int   g_cnt[MAXN];
__device__ int   g_off[MAXN];
__device__ int   g_pos[MAXN];
__device__ int   g_srt[MAXE];
__device__ int   g_bsum[256];

// ---------------------------------------------------------------------------
// f32x2 packed-FMA helpers (Blackwell FFMA2)
// ---------------------------------------------------------------------------
__device__ __forceinline__ u64 splat2(float a) {
    u64 d; asm("mov.b64 %0, {%1, %1};" : "=l"(d) : "f"(a)); return d;
}
__device__ __forceinline__ void fma2(u64& d, u64 a, u64 b) {
    asm("fma.rn.f32x2 %0, %1, %2, %0;" : "+l"(d) : "l"(a), "l"(b));
}
__device__ __forceinline__ float2 unpack2(u64 d) {
    float2 r; asm("mov.b64 {%0, %1}, %2;" : "=f"(r.x), "=f"(r.y) : "l"(d)); return r;
}

// ---------------------------------------------------------------------------
// CSR build: zero counts -> histogram -> 3-kernel exclusive scan -> fill
// ---------------------------------------------------------------------------
__global__ void hmp_zero_cnt_kernel(int n) {
    int tid = blockIdx.x * blockDim.x + threadIdx.x;
    int stride = gridDim.x * blockDim.x;
    for (int i = tid; i < n; i += stride) g_cnt[i] = 0;
}

__global__ void hmp_hist_kernel(const int* __restrict__ rows, int e) {
    int tid = blockIdx.x * blockDim.x + threadIdx.x;
    int stride = gridDim.x * blockDim.x;
    for (int i = tid; i < e; i += stride) atomicAdd(&g_cnt[rows[i]], 1);
}

__global__ void hmp_scan_blocks_kernel(int n) {
    __shared__ int wsum[8];
    int tid = threadIdx.x;
    int i = blockIdx.x * 256 + tid;
    int lane = tid & 31, w = tid >> 5;
    int v = (i < n) ? g_cnt[i] : 0;
    int s = v;
#pragma unroll
    for (int o = 1; o < 32; o <<= 1) {
        int t = __shfl_up_sync(0xffffffffu, s, o);
        if (lane >= o) s += t;
    }
    if (lane == 31) wsum[w] = s;
    __syncthreads();
    if (w == 0) {
        int ws = (lane < 8) ? wsum[lane] : 0;
#pragma unroll
        for (int o = 1; o < 8; o <<= 1) {
            int t = __shfl_up_sync(0xffffffffu, ws, o);
            if (lane >= o) ws += t;
        }
        if (lane < 8) wsum[lane] = ws;
    }
    __syncthreads();
    int base = (w > 0) ? wsum[w - 1] : 0;
    int incl = s + base;
    if (i < n) g_off[i] = incl - v;          // exclusive within block
    if (tid == 255) g_bsum[blockIdx.x] = incl;
}

__global__ void hmp_scan_bsum_kernel(int nb) {
    __shared__ int wsum[8];
    int tid = threadIdx.x;
    int lane = tid & 31, w = tid >> 5;
    int v = (tid < nb) ? g_bsum[tid] : 0;
    int s = v;
#pragma unroll
    for (int o = 1; o < 32; o <<= 1) {
        int t = __shfl_up_sync(0xffffffffu, s, o);
        if (lane >= o) s += t;
    }
    if (lane == 31) wsum[w] = s;
    __syncthreads();
    if (w == 0) {
        int ws = (lane < 8) ? wsum[lane] : 0;
#pragma unroll
        for (int o = 1; o < 8; o <<= 1) {
            int t = __shfl_up_sync(0xffffffffu, ws, o);
            if (lane >= o) ws += t;
        }
        if (lane < 8) wsum[lane] = ws;
    }
    __syncthreads();
    int base = (w > 0) ? wsum[w - 1] : 0;
    if (tid < nb) g_bsum[tid] = s + base - v;  // exclusive
}

__global__ void hmp_scan_add_kernel(int n) {
    int i = blockIdx.x * 256 + threadIdx.x;
    if (i < n) {
        int o = g_off[i] + g_bsum[blockIdx.x];
        g_off[i] = o;
        g_pos[i] = o;
    }
}

__global__ void hmp_fill_kernel(const int* __restrict__ rows,
                                const int* __restrict__ cols, int e) {
    int tid = blockIdx.x * blockDim.x + threadIdx.x;
    int stride = gridDim.x * blockDim.x;
    for (int i = tid; i < e; i += stride) {
        int p = atomicAdd(&g_pos[rows[i]], 1);
        g_srt[p] = cols[i];
    }
}

// ---------------------------------------------------------------------------
// Aggregation: warp per dst node, gather g_msg rows, write mean (no atomics)
// ---------------------------------------------------------------------------
__global__ void hmp_aggregate_kernel(int n) {
    int gw = (blockIdx.x * blockDim.x + threadIdx.x) >> 5;
    int lane = threadIdx.x & 31;
    if (gw >= n) return;
    int start = g_off[gw];
    int cnt = g_cnt[gw];
    float4 acc = make_float4(0.f, 0.f, 0.f, 0.f);
    int j = 0;
    for (; j + 4 <= cnt; j += 4) {
        int s0 = __ldg(g_srt + start + j + 0);
        int s1 = __ldg(g_srt + start + j + 1);
        int s2 = __ldg(g_srt + start + j + 2);
        int s3 = __ldg(g_srt + start + j + 3);
        float4 v0 = reinterpret_cast<const float4*>(g_msg + (size_t)s0 * DIM)[lane];
        float4 v1 = reinterpret_cast<const float4*>(g_msg + (size_t)s1 * DIM)[lane];
        float4 v2 = reinterpret_cast<const float4*>(g_msg + (size_t)s2 * DIM)[lane];
        float4 v3 = reinterpret_cast<const float4*>(g_msg + (size_t)s3 * DIM)[lane];
        acc.x += v0.x + v1.x + v2.x + v3.x;
        acc.y += v0.y + v1.y + v2.y + v3.y;
        acc.z += v0.z + v1.z + v2.z + v3.z;
        acc.w += v0.w + v1.w + v2.w + v3.w;
    }
    for (; j < cnt; ++j) {
        int s0 = __ldg(g_srt + start + j);
        float4 v0 = reinterpret_cast<const float4*>(g_msg + (size_t)s0 * DIM)[lane];
        acc.x += v0.x; acc.y += v0.y; acc.z += v0.z; acc.w += v0.w;
    }
    float inv = 1.f / ((float)cnt + 1e-8f);
    acc.x *= inv; acc.y *= inv; acc.z *= inv; acc.w *= inv;
    reinterpret_cast<float4*>(g_sum + (size_t)gw * DIM)[lane] = acc;
}

// ---------------------------------------------------------------------------
// GEMM stage, FFMA2, 512 threads as 16(tx) x 32(ty).
// Thread owns rows {ty*2+c, 64+ty*2+c} (c=0,1), packed col-pairs tx*8..+7.
// a-operand loaded as float4 over k (1 LDS.128 per row per 4 k's).
// ---------------------------------------------------------------------------
__device__ __forceinline__ void gemm2_stage(const float* __restrict__ sT,
                                            const float* __restrict__ sW,
                                            const int roff[4], int tx,
                                            u64 acc[4][4]) {
#pragma unroll 2
    for (int k0 = 0; k0 < DIM; k0 += 4) {
        float a4[4][4];
#pragma unroll
        for (int i = 0; i < 4; ++i)
            *reinterpret_cast<float4*>(a4[i]) =
                *reinterpret_cast<const float4*>(sT + roff[i] + k0);
#pragma unroll
        for (int kk = 0; kk < 4; ++kk) {
            const ulonglong2* wp =
                reinterpret_cast<const ulonglong2*>(sW + (k0 + kk) * DIM + tx * 8);
            ulonglong2 w0 = wp[0];
            ulonglong2 w1 = wp[1];
#pragma unroll
            for (int i = 0; i < 4; ++i) {
                u64 aa = splat2(a4[i][kk]);
                fma2(acc[i][0], aa, w0.x);
                fma2(acc[i][1], aa, w0.y);
                fma2(acc[i][2], aa, w1.x);
                fma2(acc[i][3], aa, w1.y);
            }
        }
    }
}

// ---------------------------------------------------------------------------
// Per-node message MLP: g_msg = relu(logmap0(x) @ W1 + b1) @ W2 + b2
// ---------------------------------------------------------------------------
__global__ __launch_bounds__(512, 1) void hmp_msg_kernel(
    const float* __restrict__ x,
    const float* __restrict__ w1, const float* __restrict__ b1,
    const float* __restrict__ w2, const float* __restrict__ b2, int n)
{
    extern __shared__ float smem[];
    float* sW1  = smem;
    float* sW2  = smem + DIM * DIM;
    float* sT   = smem + 2 * DIM * DIM;
    float* sRow = sT + BM * LDT;

    int tid = threadIdx.x;
    int m0 = blockIdx.x * BM;
    int rows = n - m0; if (rows > BM) rows = BM;

    for (int i = tid; i < DIM * DIM; i += 512) { sW1[i] = w1[i]; sW2[i] = w2[i]; }

    // logmap0 row scale: artanh(clip(||x||)) / clip(||x||). 16 warps x 8 rows.
    int warp = tid >> 5, lane = tid & 31;
#pragma unroll
    for (int r = 0; r < 8; ++r) {
        int m = warp * 8 + r;
        float p = 0.f;
        if (m < rows) {
            float4 v = reinterpret_cast<const float4*>(x + (size_t)(m0 + m) * DIM)[lane];
            p = v.x * v.x + v.y * v.y + v.z * v.z + v.w * v.w;
        }
#pragma unroll
        for (int o = 16; o; o >>= 1) p += __shfl_xor_sync(0xffffffffu, p, o);
        if (lane == 0) {
            float nrm = sqrtf(p);
            float nc = fminf(fmaxf(nrm, 1e-8f), 1.f - 1e-5f);
            sRow[m] = (m < rows) ? (atanhf(nc) / nc) : 0.f;
        }
    }
    __syncthreads();

    for (int i = tid; i < BM * (DIM / 4); i += 512) {
        int m = i >> 5, q = i & 31;
        float4 v = make_float4(0.f, 0.f, 0.f, 0.f);
        if (m < rows) v = reinterpret_cast<const float4*>(x + (size_t)(m0 + m) * DIM)[q];
        float s = sRow[m];
        v.x *= s; v.y *= s; v.z *= s; v.w *= s;
        reinterpret_cast<float4*>(sT + m * LDT)[q] = v;
    }
    __syncthreads();

    int tx = tid & 15, ty = tid >> 4;
    int roff[4];
#pragma unroll
    for (int i = 0; i < 4; ++i) roff[i] = (ty * 2 + (i & 1) + (i >> 1) * 64) * LDT;

    u64 acc[4][4];
    {
        const u64* bb = reinterpret_cast<const u64*>(b1) + tx * 4;
        u64 c0 = bb[0], c1 = bb[1], c2 = bb[2], c3 = bb[3];
#pragma unroll
        for (int i = 0; i < 4; ++i) { acc[i][0] = c0; acc[i][1] = c1; acc[i][2] = c2; acc[i][3] = c3; }
    }
    gemm2_stage(sT, sW1, roff, tx, acc);
    __syncthreads();

#pragma unroll
    for (int i = 0; i < 4; ++i) {
        float2 v0 = unpack2(acc[i][0]);
        float2 v1 = unpack2(acc[i][1]);
        float2 v2 = unpack2(acc[i][2]);
        float2 v3 = unpack2(acc[i][3]);
        float4* dst = reinterpret_cast<float4*>(sT + roff[i] + tx * 8);
        dst[0] = make_float4(fmaxf(v0.x, 0.f), fmaxf(v0.y, 0.f), fmaxf(v1.x, 0.f), fmaxf(v1.y, 0.f));
        dst[1] = make_float4(fmaxf(v2.x, 0.f), fmaxf(v2.y, 0.f), fmaxf(v3.x, 0.f), fmaxf(v3.y, 0.f));
    }
    __syncthreads();

    {
        const u64* bb = reinterpret_cast<const u64*>(b2) + tx * 4;
        u64 c0 = bb[0], c1 = bb[1], c2 = bb[2], c3 = bb[3];
#pragma unroll
        for (int i = 0; i < 4; ++i) { acc[i][0] = c0; acc[i][1] = c1; acc[i][2] = c2; acc[i][3] = c3; }
    }
    gemm2_stage(sT, sW2, roff, tx, acc);

#pragma unroll
    for (int i = 0; i < 4; ++i) {
        int m = ty * 2 + (i & 1) + (i >> 1) * 64;
        if (m < rows) {
            float2 v0 = unpack2(acc[i][0]);
            float2 v1 = unpack2(acc[i][1]);
            float2 v2 = unpack2(acc[i][2]);
            float2 v3 = unpack2(acc[i][3]);
            float4* dst = reinterpret_cast<float4*>(g_msg + (size_t)(m0 + m) * DIM + tx * 8);
            dst[0] = make_float4(v0.x, v0.y, v1.x, v1.y);
            dst[1] = make_float4(v2.x, v2.y, v3.x, v3.y);
        }
    }
}

// ---------------------------------------------------------------------------
// Update MLP + expmap0 (g_sum already holds the mean)
// ---------------------------------------------------------------------------
__global__ __launch_bounds__(512, 1) void hmp_upd_kernel(
    const float* __restrict__ w1, const float* __restrict__ b1,
    const float* __restrict__ w2, const float* __restrict__ b2,
    float* __restrict__ out, int n)
{
    extern __shared__ float smem[];
    float* sW1  = smem;
    float* sW2  = smem + DIM * DIM;
    float* sT   = smem + 2 * DIM * DIM;

    int tid = threadIdx.x;
    int m0 = blockIdx.x * BM;
    int rows = n - m0; if (rows > BM) rows = BM;

    for (int i = tid; i < DIM * DIM; i += 512) { sW1[i] = w1[i]; sW2[i] = w2[i]; }

    for (int i = tid; i < BM * (DIM / 4); i += 512) {
        int m = i >> 5, q = i & 31;
        float4 v = make_float4(0.f, 0.f, 0.f, 0.f);
        if (m < rows) v = reinterpret_cast<const float4*>(g_sum + (size_t)(m0 + m) * DIM)[q];
        reinterpret_cast<float4*>(sT + m * LDT)[q] = v;
    }
    __syncthreads();

    int tx = tid & 15, ty = tid >> 4;
    int roff[4];
#pragma unroll
    for (int i = 0; i < 4; ++i) roff[i] = (ty * 2 + (i & 1) + (i >> 1) * 64) * LDT;

    u64 acc[4][4];
    {
        const u64* bb = reinterpret_cast<const u64*>(b1) + tx * 4;
        u64 c0 = bb[0], c1 = bb[1], c2 = bb[2], c3 = bb[3];
#pragma unroll
        for (int i = 0; i < 4; ++i) { acc[i][0] = c0; acc[i][1] = c1; acc[i][2] = c2; acc[i][3] = c3; }
    }
    gemm2_stage(sT, sW1, roff, tx, acc);
    __syncthreads();

#pragma unroll
    for (int i = 0; i < 4; ++i) {
        float2 v0 = unpack2(acc[i][0]);
        float2 v1 = unpack2(acc[i][1]);
        float2 v2 = unpack2(acc[i][2]);
        float2 v3 = unpack2(acc[i][3]);
        float4* dst = reinterpret_cast<float4*>(sT + roff[i] + tx * 8);
        dst[0] = make_float4(fmaxf(v0.x, 0.f), fmaxf(v0.y, 0.f), fmaxf(v1.x, 0.f), fmaxf(v1.y, 0.f));
        dst[1] = make_float4(fmaxf(v2.x, 0.f), fmaxf(v2.y, 0.f), fmaxf(v3.x, 0.f), fmaxf(v3.y, 0.f));
    }
    __syncthreads();

    {
        const u64* bb = reinterpret_cast<const u64*>(b2) + tx * 4;
        u64 c0 = bb[0], c1 = bb[1], c2 = bb[2], c3 = bb[3];
#pragma unroll
        for (int i = 0; i < 4; ++i) { acc[i][0] = c0; acc[i][1] = c1; acc[i][2] = c2; acc[i][3] = c3; }
    }
    gemm2_stage(sT, sW2, roff, tx, acc);

    // expmap0: row norm reduced across the 16 tx lanes (shfl, no smem)
    float v[4][8];
    float scl[4];
#pragma unroll
    for (int i = 0; i < 4; ++i) {
        float2 v0 = unpack2(acc[i][0]);
        float2 v1 = unpack2(acc[i][1]);
        float2 v2 = unpack2(acc[i][2]);
        float2 v3 = unpack2(acc[i][3]);
        v[i][0] = v0.x; v[i][1] = v0.y; v[i][2] = v1.x; v[i][3] = v1.y;
        v[i][4] = v2.x; v[i][5] = v2.y; v[i][6] = v3.x; v[i][7] = v3.y;
        float s = 0.f;
#pragma unroll
        for (int j = 0; j < 8; ++j) s += v[i][j] * v[i][j];
        s += __shfl_xor_sync(0xffffffffu, s, 1);
        s += __shfl_xor_sync(0xffffffffu, s, 2);
        s += __shfl_xor_sync(0xffffffffu, s, 4);
        s += __shfl_xor_sync(0xffffffffu, s, 8);
        float nrm = sqrtf(s);
        float nc = fmaxf(nrm, 1e-8f);
        scl[i] = tanhf(nc) / nc;
    }

#pragma unroll
    for (int i = 0; i < 4; ++i) {
        int m = ty * 2 + (i & 1) + (i >> 1) * 64;
        if (m < rows) {
            float s = scl[i];
            float4* dst = reinterpret_cast<float4*>(out + (size_t)(m0 + m) * DIM + tx * 8);
            dst[0] = make_float4(v[i][0] * s, v[i][1] * s, v[i][2] * s, v[i][3] * s);
            dst[1] = make_float4(v[i][4] * s, v[i][5] * s, v[i][6] * s, v[i][7] * s);
        }
    }
}

// ---------------------------------------------------------------------------
extern "C" void kernel_launch(void* const* d_in, const int* in_sizes, int n_in,
                              void* d_out, int out_size) {
    const float* x   = (const float*)d_in[0];
    const int*   ei  = (const int*)d_in[1];
    const float* wm1 = (const float*)d_in[2];
    const float* bm1 = (const float*)d_in[3];
    const float* wm2 = (const float*)d_in[4];
    const float* bm2 = (const float*)d_in[5];
    const float* wu1 = (const float*)d_in[6];
    const float* bu1 = (const float*)d_in[7];
    const float* wu2 = (const float*)d_in[8];
    const float* bu2 = (const float*)d_in[9];
    float* out = (float*)d_out;

    int n = in_sizes[0] / DIM;     // 50000
    int e = in_sizes[1] / 2;       // 600000
    const int* rows = ei;
    const int* cols = ei + e;

    const int SMEM_BYTES = (2 * DIM * DIM + BM * LDT + BM) * (int)sizeof(float);
    cudaFuncSetAttribute(hmp_msg_kernel, cudaFuncAttributeMaxDynamicSharedMemorySize, SMEM_BYTES);
    cudaFuncSetAttribute(hmp_upd_kernel, cudaFuncAttributeMaxDynamicSharedMemorySize, SMEM_BYTES);

    int gblocks = (n + BM - 1) / BM;
    int nb = (n + 255) / 256;

    // CSR build
    hmp_zero_cnt_kernel<<<64, 256>>>(n);
    hmp_hist_kernel<<<592, 256>>>(rows, e);
    hmp_scan_blocks_kernel<<<nb, 256>>>(n);
    hmp_scan_bsum_kernel<<<1, 256>>>(nb);
    hmp_scan_add_kernel<<<nb, 256>>>(n);
    hmp_fill_kernel<<<592, 256>>>(rows, cols, e);

    // message MLP (independent of CSR build)
    hmp_msg_kernel<<<gblocks, 512, SMEM_BYTES>>>(x, wm1, bm1, wm2, bm2, n);

    // mean aggregation (needs msg + CSR)
    int ablocks = (n * 32 + 255) / 256;
    hmp_aggregate_kernel<<<ablocks, 256>>>(n);

    // update MLP + expmap0
    hmp_upd_kernel<<<gblocks, 512, SMEM_BYTES>>>(wu1, bu1, wu2, bu2, out, n);
}